// round 4
// baseline (speedup 1.0000x reference)
#include <cuda_runtime.h>
#include <cuda_fp16.h>
#include <math.h>

#define BB 64
#define NN 10
#define ID 16
#define OD 16
#define IC 6912
#define JB 24          // j-tile for k_uhat (grid 288)
#define NTH 320        // k_uhat: tid = n*32 + bp; thread owns b=2bp,2bp+1
#define RT_JB 24       // j-tile for k_route (grid 288 x 3)
#define RT_TH 256      // k_route: 8 warps x 3 groups of 10 lanes

// Packed f32x2 helpers (sm_100+ PTX)
#define FFMA2(d, a, b) asm("fma.rn.f32x2 %0, %1, %2, %0;" : "+l"(d) : "l"(a), "l"(b))
#define FADD2(d, a)    asm("add.rn.f32x2 %0, %0, %1;"     : "+l"(d) : "l"(a))

// Scratch (device globals: allocation-free). u_hat fp16 [j][b][n][o].
__device__ __half g_uhat[(size_t)IC * BB * NN * OD + 128];
__device__ float g_s[BB * NN * OD];     // s accumulator [b][n][o]
__device__ float g_vsum[BB * NN * OD];  // running sum of v over iterations

__global__ void k_zero() {
    int i = blockIdx.x * blockDim.x + threadIdx.x;
    if (i < BB * NN * OD) { g_s[i] = 0.f; g_vsum[i] = 0.f; }
}

// ───────────────────────────── Kernel A: u_hat GEMM ─────────────────────────
// Per j: [64x16] @ [16x160]. Thread = (n, b-pair). Coalesced x loads with smem
// transpose (pad 66 keeps float2 reads 8B-aligned). Double-buffered smem,
// register prefetch, f32x2 FMA. Fused pass-0 reduction (c uniform = 0.1).
__global__ __launch_bounds__(NTH) void k_uhat(const float* __restrict__ x,
                                              const float* __restrict__ W) {
    __shared__ float xs[2][ID * 66];                     // [i*66 + b]
    __shared__ __align__(16) float ws[2][NN * ID * OD];  // [n*256 + i*16 + o]
    const int tid = threadIdx.x;
    const int n = tid >> 5;       // warp == one n
    const int bp = tid & 31;
    const int b0 = 2 * bp;
    const int j0 = blockIdx.x * JB;

    uint4 wr[2];
    float xr[4];

    // prolog: load + stage j0 into buffer 0 (x coalesced: 16 floats per b row)
    {
        const int j = j0;
#pragma unroll
        for (int k = 0; k < 2; k++) {
            int f = (tid + k * NTH) * 4;
            wr[k] = *(const uint4*)(W + ((size_t)(f >> 8) * IC + j) * 256 + (f & 255));
        }
#pragma unroll
        for (int k = 0; k < 4; k++) {
            int e = tid + k * NTH;
            if (e < BB * ID) xr[k] = x[((size_t)(e >> 4) * IC + j) * ID + (e & 15)];
        }
#pragma unroll
        for (int k = 0; k < 2; k++) ((uint4*)ws[0])[tid + k * NTH] = wr[k];
#pragma unroll
        for (int k = 0; k < 4; k++) {
            int e = tid + k * NTH;
            if (e < BB * ID) xs[0][(e & 15) * 66 + (e >> 4)] = xr[k];
        }
    }

    unsigned long long s2a[8], s2b[8];  // pass-0 accumulators (per b)
#pragma unroll
    for (int k = 0; k < 8; k++) { s2a[k] = 0ull; s2b[k] = 0ull; }

    for (int jj = 0; jj < JB; jj++) {
        const int cur = jj & 1;
        __syncthreads();  // buf[cur] ready; prior reads of buf[cur^1] done

        if (jj + 1 < JB) {  // prefetch LDGs for j+1 (in flight during compute)
            const int j = j0 + jj + 1;
#pragma unroll
            for (int k = 0; k < 2; k++) {
                int f = (tid + k * NTH) * 4;
                wr[k] = *(const uint4*)(W + ((size_t)(f >> 8) * IC + j) * 256 + (f & 255));
            }
#pragma unroll
            for (int k = 0; k < 4; k++) {
                int e = tid + k * NTH;
                if (e < BB * ID) xr[k] = x[((size_t)(e >> 4) * IC + j) * ID + (e & 15)];
            }
        }

        // compute u[16] for (b0, n, j) and (b0+1, n, j)
        unsigned long long u2a[8], u2b[8];
#pragma unroll
        for (int k = 0; k < 8; k++) { u2a[k] = 0ull; u2b[k] = 0ull; }
        const ulonglong2* wb = (const ulonglong2*)(ws[cur] + n * 256);  // warp-uniform
        const float* xrow = xs[cur];
#pragma unroll
        for (int i = 0; i < ID; i++) {
            float2 xv = *(const float2*)(xrow + i * 66 + b0);  // even pad: 8B aligned
            unsigned long long xa2, xb2;
            asm("mov.b64 %0, {%1, %1};" : "=l"(xa2) : "f"(xv.x));
            asm("mov.b64 %0, {%1, %1};" : "=l"(xb2) : "f"(xv.y));
            ulonglong2 p0 = wb[i * 4 + 0], p1 = wb[i * 4 + 1];
            ulonglong2 p2 = wb[i * 4 + 2], p3 = wb[i * 4 + 3];
            FFMA2(u2a[0], xa2, p0.x); FFMA2(u2a[1], xa2, p0.y);
            FFMA2(u2a[2], xa2, p1.x); FFMA2(u2a[3], xa2, p1.y);
            FFMA2(u2a[4], xa2, p2.x); FFMA2(u2a[5], xa2, p2.y);
            FFMA2(u2a[6], xa2, p3.x); FFMA2(u2a[7], xa2, p3.y);
            FFMA2(u2b[0], xb2, p0.x); FFMA2(u2b[1], xb2, p0.y);
            FFMA2(u2b[2], xb2, p1.x); FFMA2(u2b[3], xb2, p1.y);
            FFMA2(u2b[4], xb2, p2.x); FFMA2(u2b[5], xb2, p2.y);
            FFMA2(u2b[6], xb2, p3.x); FFMA2(u2b[7], xb2, p3.y);
        }

        // store fp16 u_hat [j][b][n][o]
        {
            const int j = j0 + jj;
            __align__(16) __half2 ha[8], hb[8];
#pragma unroll
            for (int k = 0; k < 8; k++) {
                float lo, hi;
                asm("mov.b64 {%0, %1}, %2;" : "=f"(lo), "=f"(hi) : "l"(u2a[k]));
                ha[k] = __floats2half2_rn(lo, hi);
                asm("mov.b64 {%0, %1}, %2;" : "=f"(lo), "=f"(hi) : "l"(u2b[k]));
                hb[k] = __floats2half2_rn(lo, hi);
            }
            uint4* da = (uint4*)(g_uhat + ((size_t)(j * BB + b0) * NN + n) * OD);
            uint4* db = (uint4*)(g_uhat + ((size_t)(j * BB + b0 + 1) * NN + n) * OD);
            da[0] = *(uint4*)&ha[0]; da[1] = *(uint4*)&ha[4];
            db[0] = *(uint4*)&hb[0]; db[1] = *(uint4*)&hb[4];
#pragma unroll
            for (int k = 0; k < 8; k++) { FADD2(s2a[k], u2a[k]); FADD2(s2b[k], u2b[k]); }
        }

        __syncthreads();  // all reads of buf[cur] done before refill
        if (jj + 1 < JB) {
            const int nb = (jj + 1) & 1;
#pragma unroll
            for (int k = 0; k < 2; k++) ((uint4*)ws[nb])[tid + k * NTH] = wr[k];
#pragma unroll
            for (int k = 0; k < 4; k++) {
                int e = tid + k * NTH;
                if (e < BB * ID) xs[nb][(e & 15) * 66 + (e >> 4)] = xr[k];
            }
        }
    }

    float* spa = g_s + (b0 * NN + n) * OD;
    float* spb = g_s + ((b0 + 1) * NN + n) * OD;
#pragma unroll
    for (int k = 0; k < 8; k++) {
        float lo, hi;
        asm("mov.b64 {%0, %1}, %2;" : "=f"(lo), "=f"(hi) : "l"(s2a[k]));
        atomicAdd(spa + 2 * k, 0.1f * lo);
        atomicAdd(spa + 2 * k + 1, 0.1f * hi);
        asm("mov.b64 {%0, %1}, %2;" : "=f"(lo), "=f"(hi) : "l"(s2b[k]));
        atomicAdd(spb + 2 * k, 0.1f * lo);
        atomicAdd(spb + 2 * k + 1, 0.1f * hi);
    }
}

// ───────────────────────── Kernel B: squash s -> v ──────────────────────────
__global__ void k_squash(float* __restrict__ out, int final_pass) {
    int t = threadIdx.x;
    if (t >= BB * NN) return;
    float4* sp = (float4*)(g_s + t * OD);
    float4 a = sp[0], b4 = sp[1], c4 = sp[2], d4 = sp[3];
    float s[OD] = {a.x, a.y, a.z, a.w, b4.x, b4.y, b4.z, b4.w,
                   c4.x, c4.y, c4.z, c4.w, d4.x, d4.y, d4.z, d4.w};
    float s2 = 0.f;
#pragma unroll
    for (int o = 0; o < OD; o++) s2 = fmaf(s[o], s[o], s2);
    float scale = (s2 / (1.f + s2)) * rsqrtf(s2 + 1e-7f);
    if (final_pass) {
        float4* op = (float4*)(out + t * OD);
        op[0] = make_float4(scale * s[0], scale * s[1], scale * s[2], scale * s[3]);
        op[1] = make_float4(scale * s[4], scale * s[5], scale * s[6], scale * s[7]);
        op[2] = make_float4(scale * s[8], scale * s[9], scale * s[10], scale * s[11]);
        op[3] = make_float4(scale * s[12], scale * s[13], scale * s[14], scale * s[15]);
    } else {
        float* vp = g_vsum + t * OD;
#pragma unroll
        for (int o = 0; o < OD; o++) vp[o] += scale * s[o];
        float4 z = make_float4(0.f, 0.f, 0.f, 0.f);
        sp[0] = z; sp[1] = z; sp[2] = z; sp[3] = z;
    }
}

// ───────────────────────── Kernel C: routing pass ───────────────────────────
// Warp = 3 groups of 10 lanes (n = lane%10); 30/32 lanes active. Softmax via
// warp-local smem exchange: STS e, syncwarp, 3x LDS.128 (broadcast) + sum.
// No block barriers, no shfl chain. Depth-3 register prefetch.
__global__ __launch_bounds__(RT_TH) void k_route() {
    __shared__ float es[2][RT_TH / 32][3][12];  // pad slots [10..11] stay 0
    const int tid = threadIdx.x;
    const int lane = tid & 31;
    const int w = tid >> 5;
    const int g3 = lane / 10;            // 0..2 valid; 3 => idle lane
    const int n = lane - g3 * 10;
    const int g3c = (g3 < 3) ? g3 : 2;   // clamp for safe addressing
    const int b = blockIdx.y * 24 + w * 3 + g3c;
    const bool active = (g3 < 3) && (b < BB);
    const int j0 = blockIdx.x * RT_JB;

    // zero es once (establishes the zero pad slots for softmax denominator)
    for (int t = tid; t < 2 * (RT_TH / 32) * 3 * 12; t += RT_TH)
        ((float*)es)[t] = 0.f;
    __syncthreads();

    float vs[OD];
    {
        const float4* vp = (const float4*)(g_vsum + ((active ? b : 0) * NN + n % NN) * OD);
#pragma unroll
        for (int k = 0; k < 4; k++) {
            float4 v = vp[k];
            vs[4 * k] = v.x; vs[4 * k + 1] = v.y;
            vs[4 * k + 2] = v.z; vs[4 * k + 3] = v.w;
        }
    }
    float s_acc[OD];
#pragma unroll
    for (int o = 0; o < OD; o++) s_acc[o] = 0.f;

    const uint4* up = (const uint4*)(g_uhat +
        ((size_t)(j0 * BB + (active ? b : 0)) * NN + n) * OD);
    const size_t step = (BB * NN * OD) / 8;  // uint4 stride per j

    uint4 pf[3][2];  // depth-3 pipeline
#pragma unroll
    for (int k = 0; k < 3; k++) {
        const uint4* p = up + (size_t)k * step;
        pf[k][0] = p[0]; pf[k][1] = p[1];
    }

    for (int jo = 0; jo < RT_JB; jo += 3) {
#pragma unroll
        for (int sl = 0; sl < 3; sl++) {
            const int jj = jo + sl;
            const int buf = jj & 1;
            uint4 cA = pf[sl][0], cB = pf[sl][1];
            if (jj + 3 < RT_JB) {
                const uint4* nx = up + (size_t)(jj + 3) * step;
                pf[sl][0] = nx[0]; pf[sl][1] = nx[1];
            }
            float u[OD];
            {
                const __half2* hA = (const __half2*)&cA;
                const __half2* hB = (const __half2*)&cB;
#pragma unroll
                for (int k = 0; k < 4; k++) {
                    float2 f = __half22float2(hA[k]);
                    u[2 * k] = f.x; u[2 * k + 1] = f.y;
                }
#pragma unroll
                for (int k = 0; k < 4; k++) {
                    float2 f = __half22float2(hB[k]);
                    u[8 + 2 * k] = f.x; u[8 + 2 * k + 1] = f.y;
                }
            }
            float d0 = 0.f, d1 = 0.f, d2 = 0.f, d3 = 0.f;
#pragma unroll
            for (int k = 0; k < 4; k++) {
                d0 = fmaf(u[k], vs[k], d0);
                d1 = fmaf(u[4 + k], vs[4 + k], d1);
                d2 = fmaf(u[8 + k], vs[8 + k], d2);
                d3 = fmaf(u[12 + k], vs[12 + k], d3);
            }
            float d = (d0 + d1) + (d2 + d3);
            float e = __expf(d);  // |d| small: no max-shift needed
            if (active) es[buf][w][g3c][n] = e;
            __syncwarp();
            const float4* eg = (const float4*)es[buf][w][g3c];
            float4 A = eg[0], B4 = eg[1], C4 = eg[2];  // independent LDS.128
            float sum = ((A.x + A.y) + (A.z + A.w)) +
                        ((B4.x + B4.y) + (B4.z + B4.w)) +
                        ((C4.x + C4.y) + (C4.z + C4.w));
            float c = __fdividef(e, sum);
#pragma unroll
            for (int o = 0; o < OD; o++) s_acc[o] = fmaf(c, u[o], s_acc[o]);
        }
    }

    if (active) {
        float* sp = g_s + (b * NN + n) * OD;
#pragma unroll
        for (int o = 0; o < OD; o++) atomicAdd(sp + o, s_acc[o]);
    }
}

extern "C" void kernel_launch(void* const* d_in, const int* in_sizes, int n_in,
                              void* d_out, int out_size) {
    const float* x = (const float*)d_in[0];  // [64, 6912, 16]
    const float* W = (const float*)d_in[1];  // [10, 6912, 16, 16]
    float* out = (float*)d_out;              // [64, 10, 16]

    dim3 rgrid(IC / RT_JB, 3);  // 3*24 = 72 >= 64 b's (guarded)

    k_zero<<<(BB * NN * OD + 255) / 256, 256>>>();
    k_uhat<<<IC / JB, NTH>>>(x, W);   // u_hat (fp16) + fused s0 (uniform c)
    k_squash<<<1, 640>>>(out, 0);     // v0; vsum = v0
    k_route<<<rgrid, RT_TH>>>();      // s1, logits = u_hat . v0
    k_squash<<<1, 640>>>(out, 0);     // v1; vsum = v0 + v1
    k_route<<<rgrid, RT_TH>>>();      // s2, logits = u_hat . (v0+v1)
    k_squash<<<1, 640>>>(out, 1);     // v2 -> output
}

// round 5
// speedup vs baseline: 1.1277x; 1.1277x over previous
#include <cuda_runtime.h>
#include <cuda_fp16.h>
#include <math.h>

#define BB 64
#define NN 10
#define ID 16
#define OD 16
#define IC 6912
#define JB 24          // j-tile for k_uhat (grid 288, 2 blocks/SM)
#define NTH 320        // k_uhat: tid = n*32 + bp; thread owns b=2bp,2bp+1 (sequential)
#define RT_JB 32       // j-tile for k_route (grid 216 x 4 = 864)
#define RT_TH 256      // k_route: 16-lane groups, n = tid&15

// Packed f32x2 helpers (sm_100+ PTX)
#define FFMA2(d, a, b) asm("fma.rn.f32x2 %0, %1, %2, %0;" : "+l"(d) : "l"(a), "l"(b))
#define FADD2(d, a)    asm("add.rn.f32x2 %0, %0, %1;"     : "+l"(d) : "l"(a))

// Scratch (device globals: allocation-free). u_hat fp16 [j][b][n][o].
__device__ __half g_uhat[(size_t)IC * BB * NN * OD + 128];
__device__ float g_s[BB * NN * OD];     // s accumulator [b][n][o]
__device__ float g_vsum[BB * NN * OD];  // running sum of v over iterations

__global__ void k_zero() {
    int i = blockIdx.x * blockDim.x + threadIdx.x;
    if (i < BB * NN * OD) { g_s[i] = 0.f; g_vsum[i] = 0.f; }
}

__global__ void k_nop() {}  // launch-order shims so ncu (-s 5) profiles k_uhat

// ───────────────────────────── Kernel A: u_hat GEMM ─────────────────────────
// Per j: [64x16] @ [16x160]. Thread owns b-pair, processed SEQUENTIALLY to keep
// regs <= 102 (guaranteed 2 blocks/SM -> barriers of the two blocks overlap).
// Double-buffered smem, register prefetch, f32x2 FMA, fused s0 (c = 0.1).
__global__ __launch_bounds__(NTH, 2) void k_uhat(const float* __restrict__ x,
                                                 const float* __restrict__ W) {
    __shared__ float xs[2][ID * 66];                     // [i*66 + b]
    __shared__ __align__(16) float ws[2][NN * ID * OD];  // [n*256 + i*16 + o]
    const int tid = threadIdx.x;
    const int n = tid >> 5;       // warp == one n
    const int bp = tid & 31;
    const int b0 = 2 * bp;
    const int j0 = blockIdx.x * JB;

    uint4 wr[2];
    float xr[4];

    // prolog: load + stage j0 into buffer 0 (x coalesced)
    {
        const int j = j0;
#pragma unroll
        for (int k = 0; k < 2; k++) {
            int f = (tid + k * NTH) * 4;
            wr[k] = *(const uint4*)(W + ((size_t)(f >> 8) * IC + j) * 256 + (f & 255));
        }
#pragma unroll
        for (int k = 0; k < 4; k++) {
            int e = tid + k * NTH;
            if (e < BB * ID) xr[k] = x[((size_t)(e >> 4) * IC + j) * ID + (e & 15)];
        }
#pragma unroll
        for (int k = 0; k < 2; k++) ((uint4*)ws[0])[tid + k * NTH] = wr[k];
#pragma unroll
        for (int k = 0; k < 4; k++) {
            int e = tid + k * NTH;
            if (e < BB * ID) xs[0][(e & 15) * 66 + (e >> 4)] = xr[k];
        }
    }

    unsigned long long s2[2][8];  // pass-0 accumulators (fp32 pairs per b)
#pragma unroll
    for (int k = 0; k < 8; k++) { s2[0][k] = 0ull; s2[1][k] = 0ull; }

    for (int jj = 0; jj < JB; jj++) {
        const int cur = jj & 1;
        __syncthreads();  // buf[cur] ready; prior reads of buf[cur^1] done

        if (jj + 1 < JB) {  // prefetch LDGs for j+1 (in flight during compute)
            const int j = j0 + jj + 1;
#pragma unroll
            for (int k = 0; k < 2; k++) {
                int f = (tid + k * NTH) * 4;
                wr[k] = *(const uint4*)(W + ((size_t)(f >> 8) * IC + j) * 256 + (f & 255));
            }
#pragma unroll
            for (int k = 0; k < 4; k++) {
                int e = tid + k * NTH;
                if (e < BB * ID) xr[k] = x[((size_t)(e >> 4) * IC + j) * ID + (e & 15)];
            }
        }

        const ulonglong2* wb = (const ulonglong2*)(ws[cur] + n * 256);  // warp-uniform
        const float* xrow = xs[cur];
        const int j = j0 + jj;

#pragma unroll
        for (int bb = 0; bb < 2; bb++) {   // sequential b: only one u2[8] live
            unsigned long long u2[8];
#pragma unroll
            for (int k = 0; k < 8; k++) u2[k] = 0ull;
#pragma unroll
            for (int i = 0; i < ID; i++) {
                float xv = xrow[i * 66 + b0 + bb];
                unsigned long long xv2;
                asm("mov.b64 %0, {%1, %1};" : "=l"(xv2) : "f"(xv));
                ulonglong2 p0 = wb[i * 4 + 0], p1 = wb[i * 4 + 1];
                ulonglong2 p2 = wb[i * 4 + 2], p3 = wb[i * 4 + 3];
                FFMA2(u2[0], xv2, p0.x); FFMA2(u2[1], xv2, p0.y);
                FFMA2(u2[2], xv2, p1.x); FFMA2(u2[3], xv2, p1.y);
                FFMA2(u2[4], xv2, p2.x); FFMA2(u2[5], xv2, p2.y);
                FFMA2(u2[6], xv2, p3.x); FFMA2(u2[7], xv2, p3.y);
            }
            __align__(16) __half2 h[8];
#pragma unroll
            for (int k = 0; k < 8; k++) {
                float lo, hi;
                asm("mov.b64 {%0, %1}, %2;" : "=f"(lo), "=f"(hi) : "l"(u2[k]));
                h[k] = __floats2half2_rn(lo, hi);
            }
            uint4* dst = (uint4*)(g_uhat + ((size_t)(j * BB + b0 + bb) * NN + n) * OD);
            dst[0] = *(uint4*)&h[0];
            dst[1] = *(uint4*)&h[4];
#pragma unroll
            for (int k = 0; k < 8; k++) FADD2(s2[bb][k], u2[k]);
        }

        __syncthreads();  // all reads of buf[cur] done before refill
        if (jj + 1 < JB) {
            const int nb = (jj + 1) & 1;
#pragma unroll
            for (int k = 0; k < 2; k++) ((uint4*)ws[nb])[tid + k * NTH] = wr[k];
#pragma unroll
            for (int k = 0; k < 4; k++) {
                int e = tid + k * NTH;
                if (e < BB * ID) xs[nb][(e & 15) * 66 + (e >> 4)] = xr[k];
            }
        }
    }

#pragma unroll
    for (int bb = 0; bb < 2; bb++) {
        float* sp = g_s + ((b0 + bb) * NN + n) * OD;
#pragma unroll
        for (int k = 0; k < 8; k++) {
            float lo, hi;
            asm("mov.b64 {%0, %1}, %2;" : "=f"(lo), "=f"(hi) : "l"(s2[bb][k]));
            atomicAdd(sp + 2 * k, 0.1f * lo);
            atomicAdd(sp + 2 * k + 1, 0.1f * hi);
        }
    }
}

// ───────────────────────── Kernel B: squash s -> v ──────────────────────────
__global__ void k_squash(float* __restrict__ out, int final_pass) {
    int t = threadIdx.x;
    if (t >= BB * NN) return;
    float4* sp = (float4*)(g_s + t * OD);
    float4 a = sp[0], b4 = sp[1], c4 = sp[2], d4 = sp[3];
    float s[OD] = {a.x, a.y, a.z, a.w, b4.x, b4.y, b4.z, b4.w,
                   c4.x, c4.y, c4.z, c4.w, d4.x, d4.y, d4.z, d4.w};
    float s2 = 0.f;
#pragma unroll
    for (int o = 0; o < OD; o++) s2 = fmaf(s[o], s[o], s2);
    float scale = (s2 / (1.f + s2)) * rsqrtf(s2 + 1e-7f);
    if (final_pass) {
        float4* op = (float4*)(out + t * OD);
        op[0] = make_float4(scale * s[0], scale * s[1], scale * s[2], scale * s[3]);
        op[1] = make_float4(scale * s[4], scale * s[5], scale * s[6], scale * s[7]);
        op[2] = make_float4(scale * s[8], scale * s[9], scale * s[10], scale * s[11]);
        op[3] = make_float4(scale * s[12], scale * s[13], scale * s[14], scale * s[15]);
    } else {
        float* vp = g_vsum + t * OD;
#pragma unroll
        for (int o = 0; o < OD; o++) vp[o] += scale * s[o];
        float4 z = make_float4(0.f, 0.f, 0.f, 0.f);
        sp[0] = z; sp[1] = z; sp[2] = z; sp[3] = z;
    }
}

// ───────────────────────── Kernel C: routing pass ───────────────────────────
// 16-lane groups (n = tid&15, ghosts n>=10 load nothing). 2-j batches: the two
// 4-step shfl softmax chains are interleaved (one chain-latency per batch).
// Logit dot in __hfma2 (vs kept as half2: 8 regs). u stays packed; converted
// per use. Target <=84 regs -> 3 blocks/SM (24 warps).
__global__ __launch_bounds__(RT_TH, 3) void k_route() {
    const int tid = threadIdx.x;
    const int n = tid & 15;
    const int b = blockIdx.y * 16 + (tid >> 4);
    const bool act = (n < NN);
    const int j0 = blockIdx.x * RT_JB;

    __half2 vs2[8];
    {
        const float4* vp = (const float4*)(g_vsum + (b * NN + (act ? n : 0)) * OD);
#pragma unroll
        for (int k = 0; k < 4; k++) {
            float4 v = vp[k];
            vs2[2 * k] = __floats2half2_rn(v.x, v.y);
            vs2[2 * k + 1] = __floats2half2_rn(v.z, v.w);
        }
    }
    float s_acc[OD];
#pragma unroll
    for (int o = 0; o < OD; o++) s_acc[o] = 0.f;

    const uint4* up = (const uint4*)(g_uhat + ((size_t)(j0 * BB + b) * NN + n) * OD);
    const size_t step = (BB * NN * OD) / 8;  // uint4 stride per j

    uint4 pA0 = make_uint4(0, 0, 0, 0), pB0 = pA0, pA1 = pA0, pB1 = pA0;
    if (act) { pA0 = up[0]; pB0 = up[1]; pA1 = up[step]; pB1 = up[step + 1]; }

    for (int jo = 0; jo < RT_JB; jo += 2) {
        uint4 cA0 = pA0, cB0 = pB0, cA1 = pA1, cB1 = pB1;
        if (jo + 2 < RT_JB && act) {
            const uint4* nx = up + (size_t)(jo + 2) * step;
            pA0 = nx[0]; pB0 = nx[1];
            pA1 = nx[step]; pB1 = nx[step + 1];
        }
        const __half2* h0 = (const __half2*)&cA0;  // h0[0..3], then cB0
        const __half2* g0 = (const __half2*)&cB0;
        const __half2* h1 = (const __half2*)&cA1;
        const __half2* g1 = (const __half2*)&cB1;

        // logit dots in half2 (two chains each, then combine)
        __half2 dA0 = __hmul2(h0[0], vs2[0]), dB0 = __hmul2(g0[0], vs2[4]);
        __half2 dA1 = __hmul2(h1[0], vs2[0]), dB1 = __hmul2(g1[0], vs2[4]);
#pragma unroll
        for (int k = 1; k < 4; k++) {
            dA0 = __hfma2(h0[k], vs2[k], dA0); dB0 = __hfma2(g0[k], vs2[4 + k], dB0);
            dA1 = __hfma2(h1[k], vs2[k], dA1); dB1 = __hfma2(g1[k], vs2[4 + k], dB1);
        }
        __half2 ds0 = __hadd2(dA0, dB0), ds1 = __hadd2(dA1, dB1);
        float d0 = __low2float(ds0) + __high2float(ds0);
        float d1 = __low2float(ds1) + __high2float(ds1);

        float e0 = act ? __expf(d0) : 0.f;
        float e1 = act ? __expf(d1) : 0.f;
        float s0 = e0, s1 = e1;
#pragma unroll
        for (int m = 1; m < 16; m <<= 1) {  // interleaved chains
            s0 += __shfl_xor_sync(0xFFFFFFFFu, s0, m, 16);
            s1 += __shfl_xor_sync(0xFFFFFFFFu, s1, m, 16);
        }
        float c0 = __fdividef(e0, s0);
        float c1 = __fdividef(e1, s1);

#pragma unroll
        for (int k = 0; k < 4; k++) {
            float2 f = __half22float2(h0[k]);
            s_acc[2 * k] = fmaf(c0, f.x, s_acc[2 * k]);
            s_acc[2 * k + 1] = fmaf(c0, f.y, s_acc[2 * k + 1]);
            f = __half22float2(g0[k]);
            s_acc[8 + 2 * k] = fmaf(c0, f.x, s_acc[8 + 2 * k]);
            s_acc[9 + 2 * k] = fmaf(c0, f.y, s_acc[9 + 2 * k]);
            f = __half22float2(h1[k]);
            s_acc[2 * k] = fmaf(c1, f.x, s_acc[2 * k]);
            s_acc[2 * k + 1] = fmaf(c1, f.y, s_acc[2 * k + 1]);
            f = __half22float2(g1[k]);
            s_acc[8 + 2 * k] = fmaf(c1, f.x, s_acc[8 + 2 * k]);
            s_acc[9 + 2 * k] = fmaf(c1, f.y, s_acc[9 + 2 * k]);
        }
    }

    if (act) {
        float* sp = g_s + (b * NN + n) * OD;
#pragma unroll
        for (int o = 0; o < OD; o++) atomicAdd(sp + o, s_acc[o]);
    }
}

extern "C" void kernel_launch(void* const* d_in, const int* in_sizes, int n_in,
                              void* d_out, int out_size) {
    const float* x = (const float*)d_in[0];  // [64, 6912, 16]
    const float* W = (const float*)d_in[1];  // [10, 6912, 16, 16]
    float* out = (float*)d_out;              // [64, 10, 16]

    dim3 rgrid(IC / RT_JB, BB / 16);  // (216, 4)

    k_zero<<<(BB * NN * OD + 255) / 256, 256>>>();
    k_nop<<<1, 32>>>();  // shims: make k_uhat the 6th launch (ncu -s 5 -c 1)
    k_nop<<<1, 32>>>();
    k_nop<<<1, 32>>>();
    k_nop<<<1, 32>>>();
    k_uhat<<<IC / JB, NTH>>>(x, W);   // u_hat (fp16) + fused s0 (uniform c)
    k_squash<<<1, 640>>>(out, 0);     // v0; vsum = v0
    k_route<<<rgrid, RT_TH>>>();      // s1, logits = u_hat . v0
    k_squash<<<1, 640>>>(out, 0);     // v1; vsum = v0 + v1
    k_route<<<rgrid, RT_TH>>>();      // s2, logits = u_hat . (v0+v1)
    k_squash<<<1, 640>>>(out, 1);     // v2 -> output
}

// round 6
// speedup vs baseline: 1.2705x; 1.1266x over previous
#include <cuda_runtime.h>
#include <cuda_fp16.h>
#include <math.h>

#define BB 64
#define NN 10
#define ID 16
#define OD 16
#define IC 6912
#define JB 24          // j-tile for k_uhat (grid 288, 2 blocks/SM)
#define NTH 320        // k_uhat: tid = n*32 + bp; thread owns b=2bp,2bp+1 (sequential)
#define JT 16          // j's per k_xt block
#define RT_JB 32       // j-tile for k_route (grid 216 x 4 = 864)
#define RT_TH 256      // k_route: 16-lane groups, n = tid&15

// Packed f32x2 helpers (sm_100+ PTX)
#define FFMA2(d, a, b) asm("fma.rn.f32x2 %0, %1, %2, %0;" : "+l"(d) : "l"(a), "l"(b))
#define FADD2(d, a)    asm("add.rn.f32x2 %0, %0, %1;"     : "+l"(d) : "l"(a))
// cp.async (LDGSTS)
#define CP16(dst, src) asm volatile("cp.async.ca.shared.global [%0], [%1], 16;" \
                                    :: "r"(dst), "l"(src))
#define CP_COMMIT()    asm volatile("cp.async.commit_group;")
#define CP_WAIT2()     asm volatile("cp.async.wait_group 2;")

// Scratch (device globals: allocation-free). u_hat fp16 [j][b][n][o].
__device__ __half g_uhat[(size_t)IC * BB * NN * OD + 128];
__device__ float g_xT[(size_t)IC * ID * BB];  // x transposed: [j][i][b]
__device__ float g_s[BB * NN * OD];           // s accumulator [b][n][o]
__device__ float g_vsum[BB * NN * OD];        // running sum of v

__global__ void k_zero() {
    int i = blockIdx.x * blockDim.x + threadIdx.x;
    if (i < BB * NN * OD) { g_s[i] = 0.f; g_vsum[i] = 0.f; }
}

// ─────────────── Kernel T: transpose x [b][j][i] -> xT [j][i][b] ───────────
__global__ void k_xt(const float* __restrict__ x) {
    __shared__ float t[ID][66];
    const int tid = threadIdx.x;  // 256
    const int jb = blockIdx.x * JT;
    for (int jj = 0; jj < JT; jj++) {
        const int j = jb + jj;
#pragma unroll
        for (int r = 0; r < 4; r++) {
            int e = r * 256 + tid;
            t[e & 15][e >> 4] = x[((size_t)(e >> 4) * IC + j) * 16 + (e & 15)];
        }
        __syncthreads();
#pragma unroll
        for (int r = 0; r < 4; r++) {
            int o = r * 256 + tid;
            g_xT[(size_t)j * (ID * BB) + o] = t[o >> 6][o & 63];
        }
        __syncthreads();
    }
}

// ───────────────────────────── Kernel A: u_hat GEMM ─────────────────────────
// 4-stage cp.async pipeline: 3 stages (42 KB/block) outstanding continuously
// -> latency-covered DRAM streaming. One barrier + one wait_group per j.
// Compute: thread = (n, b-pair) sequential, f32x2 FMA, fused s0 (c = 0.1).
__global__ __launch_bounds__(NTH, 2) void k_uhat(const float* __restrict__ W) {
    __shared__ __align__(16) float stg[4][3584];  // per stage: ws[2560] + xs[1024]
    const int tid = threadIdx.x;
    const int n = tid >> 5;
    const int bp = tid & 31;
    const int b0 = 2 * bp;
    const int j0 = blockIdx.x * JB;

    // per-thread fixed source offsets (chunk c -> n=c>>6, 16B off=(c&63)*4)
    const float* wsrc1 = W + (size_t)(tid >> 6) * IC * 256 + (tid & 63) * 4;
    const float* wsrc2 = W + (size_t)((tid + 320) >> 6) * IC * 256 + ((tid + 320) & 63) * 4;
    const unsigned wdst1 = (unsigned)__cvta_generic_to_shared(&stg[0][tid * 4]);
    const unsigned wdst2 = (unsigned)__cvta_generic_to_shared(&stg[0][(tid + 320) * 4]);
    const unsigned xdst = (unsigned)__cvta_generic_to_shared(&stg[0][2560 + tid * 4]);
    const unsigned sstride = 3584 * 4;  // bytes per stage

#define ISSUE(jv, sv)                                                        \
    do {                                                                     \
        CP16(wdst1 + (sv) * sstride, wsrc1 + (size_t)(jv) * 256);            \
        CP16(wdst2 + (sv) * sstride, wsrc2 + (size_t)(jv) * 256);            \
        if (tid < 256)                                                       \
            CP16(xdst + (sv) * sstride, g_xT + (size_t)(jv) * 1024 + tid * 4); \
    } while (0)

    // prologue: stages 0..2
#pragma unroll
    for (int s = 0; s < 3; s++) { ISSUE(j0 + s, s); CP_COMMIT(); }

    unsigned long long s2[2][8];  // pass-0 accumulators (fp32 pairs per b)
#pragma unroll
    for (int k = 0; k < 8; k++) { s2[0][k] = 0ull; s2[1][k] = 0ull; }

    for (int jj = 0; jj < JB; jj++) {
        CP_WAIT2();        // stage jj landed (for this thread's copies)
        __syncthreads();   // ...for all threads; also fences reuse of stage (jj+3)&3

        const int cur = jj & 3;
        const float* ws = stg[cur];
        const float* xsm = ws + 2560;
        const ulonglong2* wb = (const ulonglong2*)(ws + n * 256);  // warp-uniform
        const int j = j0 + jj;

#pragma unroll
        for (int bb = 0; bb < 2; bb++) {   // sequential b: one u2[8] live
            unsigned long long u2[8];
#pragma unroll
            for (int k = 0; k < 8; k++) u2[k] = 0ull;
#pragma unroll
            for (int i = 0; i < ID; i++) {
                float xv = xsm[i * 64 + b0 + bb];  // 2-way conflict, acceptable
                unsigned long long xv2;
                asm("mov.b64 %0, {%1, %1};" : "=l"(xv2) : "f"(xv));
                ulonglong2 p0 = wb[i * 4 + 0], p1 = wb[i * 4 + 1];
                ulonglong2 p2 = wb[i * 4 + 2], p3 = wb[i * 4 + 3];
                FFMA2(u2[0], xv2, p0.x); FFMA2(u2[1], xv2, p0.y);
                FFMA2(u2[2], xv2, p1.x); FFMA2(u2[3], xv2, p1.y);
                FFMA2(u2[4], xv2, p2.x); FFMA2(u2[5], xv2, p2.y);
                FFMA2(u2[6], xv2, p3.x); FFMA2(u2[7], xv2, p3.y);
            }
            __align__(16) __half2 h[8];
#pragma unroll
            for (int k = 0; k < 8; k++) {
                float lo, hi;
                asm("mov.b64 {%0, %1}, %2;" : "=f"(lo), "=f"(hi) : "l"(u2[k]));
                h[k] = __floats2half2_rn(lo, hi);
            }
            uint4* dst = (uint4*)(g_uhat + ((size_t)(j * BB + b0 + bb) * NN + n) * OD);
            dst[0] = *(uint4*)&h[0];
            dst[1] = *(uint4*)&h[4];
#pragma unroll
            for (int k = 0; k < 8; k++) FADD2(s2[bb][k], u2[k]);
        }

        // refill stage (jj+3)&3 (== (jj-1)&3, safe: barrier above fenced its readers)
        if (jj + 3 < JB) ISSUE(j0 + jj + 3, (jj + 3) & 3);
        CP_COMMIT();  // commit every iter (possibly empty) to keep group counts uniform
    }
#undef ISSUE

#pragma unroll
    for (int bb = 0; bb < 2; bb++) {
        float* sp = g_s + ((b0 + bb) * NN + n) * OD;
#pragma unroll
        for (int k = 0; k < 8; k++) {
            float lo, hi;
            asm("mov.b64 {%0, %1}, %2;" : "=f"(lo), "=f"(hi) : "l"(s2[bb][k]));
            atomicAdd(sp + 2 * k, 0.1f * lo);
            atomicAdd(sp + 2 * k + 1, 0.1f * hi);
        }
    }
}

// ───────────────────────── Kernel B: squash s -> v ──────────────────────────
__global__ void k_squash(float* __restrict__ out, int final_pass) {
    int t = threadIdx.x;
    if (t >= BB * NN) return;
    float4* sp = (float4*)(g_s + t * OD);
    float4 a = sp[0], b4 = sp[1], c4 = sp[2], d4 = sp[3];
    float s[OD] = {a.x, a.y, a.z, a.w, b4.x, b4.y, b4.z, b4.w,
                   c4.x, c4.y, c4.z, c4.w, d4.x, d4.y, d4.z, d4.w};
    float s2 = 0.f;
#pragma unroll
    for (int o = 0; o < OD; o++) s2 = fmaf(s[o], s[o], s2);
    float scale = (s2 / (1.f + s2)) * rsqrtf(s2 + 1e-7f);
    if (final_pass) {
        float4* op = (float4*)(out + t * OD);
        op[0] = make_float4(scale * s[0], scale * s[1], scale * s[2], scale * s[3]);
        op[1] = make_float4(scale * s[4], scale * s[5], scale * s[6], scale * s[7]);
        op[2] = make_float4(scale * s[8], scale * s[9], scale * s[10], scale * s[11]);
        op[3] = make_float4(scale * s[12], scale * s[13], scale * s[14], scale * s[15]);
    } else {
        float* vp = g_vsum + t * OD;
#pragma unroll
        for (int o = 0; o < OD; o++) vp[o] += scale * s[o];
        float4 z = make_float4(0.f, 0.f, 0.f, 0.f);
        sp[0] = z; sp[1] = z; sp[2] = z; sp[3] = z;
    }
}

// ───────────────────────── Kernel C: routing pass ───────────────────────────
// 16-lane groups (n = tid&15, ghosts load nothing). 2-j batches with the two
// shfl softmax chains interleaved. Logit dot in __hfma2.
__global__ __launch_bounds__(RT_TH, 3) void k_route() {
    const int tid = threadIdx.x;
    const int n = tid & 15;
    const int b = blockIdx.y * 16 + (tid >> 4);
    const bool act = (n < NN);
    const int j0 = blockIdx.x * RT_JB;

    __half2 vs2[8];
    {
        const float4* vp = (const float4*)(g_vsum + (b * NN + (act ? n : 0)) * OD);
#pragma unroll
        for (int k = 0; k < 4; k++) {
            float4 v = vp[k];
            vs2[2 * k] = __floats2half2_rn(v.x, v.y);
            vs2[2 * k + 1] = __floats2half2_rn(v.z, v.w);
        }
    }
    float s_acc[OD];
#pragma unroll
    for (int o = 0; o < OD; o++) s_acc[o] = 0.f;

    const uint4* up = (const uint4*)(g_uhat + ((size_t)(j0 * BB + b) * NN + n) * OD);
    const size_t step = (BB * NN * OD) / 8;  // uint4 stride per j

    uint4 pA0 = make_uint4(0, 0, 0, 0), pB0 = pA0, pA1 = pA0, pB1 = pA0;
    if (act) { pA0 = up[0]; pB0 = up[1]; pA1 = up[step]; pB1 = up[step + 1]; }

    for (int jo = 0; jo < RT_JB; jo += 2) {
        uint4 cA0 = pA0, cB0 = pB0, cA1 = pA1, cB1 = pB1;
        if (jo + 2 < RT_JB && act) {
            const uint4* nx = up + (size_t)(jo + 2) * step;
            pA0 = nx[0]; pB0 = nx[1];
            pA1 = nx[step]; pB1 = nx[step + 1];
        }
        const __half2* h0 = (const __half2*)&cA0;
        const __half2* g0 = (const __half2*)&cB0;
        const __half2* h1 = (const __half2*)&cA1;
        const __half2* g1 = (const __half2*)&cB1;

        __half2 dA0 = __hmul2(h0[0], vs2[0]), dB0 = __hmul2(g0[0], vs2[4]);
        __half2 dA1 = __hmul2(h1[0], vs2[0]), dB1 = __hmul2(g1[0], vs2[4]);
#pragma unroll
        for (int k = 1; k < 4; k++) {
            dA0 = __hfma2(h0[k], vs2[k], dA0); dB0 = __hfma2(g0[k], vs2[4 + k], dB0);
            dA1 = __hfma2(h1[k], vs2[k], dA1); dB1 = __hfma2(g1[k], vs2[4 + k], dB1);
        }
        __half2 ds0 = __hadd2(dA0, dB0), ds1 = __hadd2(dA1, dB1);
        float d0 = __low2float(ds0) + __high2float(ds0);
        float d1 = __low2float(ds1) + __high2float(ds1);

        float e0 = act ? __expf(d0) : 0.f;
        float e1 = act ? __expf(d1) : 0.f;
        float s0 = e0, s1 = e1;
#pragma unroll
        for (int m = 1; m < 16; m <<= 1) {  // interleaved chains
            s0 += __shfl_xor_sync(0xFFFFFFFFu, s0, m, 16);
            s1 += __shfl_xor_sync(0xFFFFFFFFu, s1, m, 16);
        }
        float c0 = __fdividef(e0, s0);
        float c1 = __fdividef(e1, s1);

#pragma unroll
        for (int k = 0; k < 4; k++) {
            float2 f = __half22float2(h0[k]);
            s_acc[2 * k] = fmaf(c0, f.x, s_acc[2 * k]);
            s_acc[2 * k + 1] = fmaf(c0, f.y, s_acc[2 * k + 1]);
            f = __half22float2(g0[k]);
            s_acc[8 + 2 * k] = fmaf(c0, f.x, s_acc[8 + 2 * k]);
            s_acc[9 + 2 * k] = fmaf(c0, f.y, s_acc[9 + 2 * k]);
            f = __half22float2(h1[k]);
            s_acc[2 * k] = fmaf(c1, f.x, s_acc[2 * k]);
            s_acc[2 * k + 1] = fmaf(c1, f.y, s_acc[2 * k + 1]);
            f = __half22float2(g1[k]);
            s_acc[8 + 2 * k] = fmaf(c1, f.x, s_acc[8 + 2 * k]);
            s_acc[9 + 2 * k] = fmaf(c1, f.y, s_acc[9 + 2 * k]);
        }
    }

    if (act) {
        float* sp = g_s + (b * NN + n) * OD;
#pragma unroll
        for (int o = 0; o < OD; o++) atomicAdd(sp + o, s_acc[o]);
    }
}

extern "C" void kernel_launch(void* const* d_in, const int* in_sizes, int n_in,
                              void* d_out, int out_size) {
    const float* x = (const float*)d_in[0];  // [64, 6912, 16]
    const float* W = (const float*)d_in[1];  // [10, 6912, 16, 16]
    float* out = (float*)d_out;              // [64, 10, 16]

    dim3 rgrid(IC / RT_JB, BB / 16);  // (216, 4)

    k_zero<<<(BB * NN * OD + 255) / 256, 256>>>();
    k_xt<<<IC / JT, 256>>>(x);        // x -> xT [j][i][b]
    k_uhat<<<IC / JB, NTH>>>(W);      // u_hat (fp16) + fused s0 (uniform c)
    k_squash<<<1, 640>>>(out, 0);     // v0; vsum = v0
    k_route<<<rgrid, RT_TH>>>();      // s1, logits = u_hat . v0
    k_squash<<<1, 640>>>(out, 0);     // v1; vsum = v0 + v1
    k_route<<<rgrid, RT_TH>>>();      // s2, logits = u_hat . (v0+v1)
    k_squash<<<1, 640>>>(out, 1);     // v2 -> output
}

// round 7
// speedup vs baseline: 1.2990x; 1.0225x over previous
#include <cuda_runtime.h>
#include <cuda_fp16.h>
#include <math.h>

#define BB 64
#define NN 10
#define ID 16
#define OD 16
#define IC 6912
#define JB 24          // j-tile for k_uhat (grid 288, 2 blocks/SM)
#define NTH 320        // k_uhat: warp = n; thread owns b-pair (interleaved)
#define JT 16          // j's per k_xt block
#define RT_JB 32       // j-tile for k_route (grid 216 x 4 = 864)
#define RT_TH 256      // k_route: 16-lane groups, n = tid&15

// Packed f32x2 helpers (sm_100+ PTX)
#define FFMA2(d, a, b) asm("fma.rn.f32x2 %0, %1, %2, %0;" : "+l"(d) : "l"(a), "l"(b))
#define FADD2(d, a)    asm("add.rn.f32x2 %0, %0, %1;"     : "+l"(d) : "l"(a))
// cp.async (LDGSTS)
#define CP16(dst, src) asm volatile("cp.async.ca.shared.global [%0], [%1], 16;" \
                                    :: "r"(dst), "l"(src))
#define CP_COMMIT()    asm volatile("cp.async.commit_group;")
#define CP_WAIT2()     asm volatile("cp.async.wait_group 2;")

// Scratch (device globals: allocation-free). u_hat fp16 [j][b][n][o].
__device__ __half g_uhat[(size_t)IC * BB * NN * OD + 128];
__device__ float g_xT[(size_t)IC * ID * BB];  // x transposed: [j][i][b]
__device__ float g_s0[BB * NN * OD];          // s from pass 0 (uhat epilogue)
__device__ float g_s1[BB * NN * OD];          // s from pass 1 (route 1)
__device__ float g_s2[BB * NN * OD];          // s from pass 2 (route 2)

__global__ void k_nop() {}  // shims: put k_uhat at ncu's -s 5 -c 1 slot

// ─────────── Kernel T: transpose x -> xT [j][i][b]; also zero g_s* ──────────
__global__ void k_xt(const float* __restrict__ x) {
    __shared__ float t[ID][66];
    const int tid = threadIdx.x;  // 256
    const int bid = blockIdx.x;
    if (bid < 30) {  // zero 3 x 10240 floats of s buffers
        float* z = (bid < 10) ? g_s0 : (bid < 20) ? g_s1 : g_s2;
        int off = (bid % 10) * 1024;
#pragma unroll
        for (int r = 0; r < 4; r++) z[off + r * 256 + tid] = 0.f;
    }
    const int jb = bid * JT;
    for (int jj = 0; jj < JT; jj++) {
        const int j = jb + jj;
#pragma unroll
        for (int r = 0; r < 4; r++) {
            int e = r * 256 + tid;
            t[e & 15][e >> 4] = x[((size_t)(e >> 4) * IC + j) * 16 + (e & 15)];
        }
        __syncthreads();
#pragma unroll
        for (int r = 0; r < 4; r++) {
            int o = r * 256 + tid;
            g_xT[(size_t)j * (ID * BB) + o] = t[o >> 6][o & 63];
        }
        __syncthreads();
    }
}

// ───────────────────────────── Kernel A: u_hat GEMM ─────────────────────────
// 4-stage cp.async pipeline (3 stages / 42 KB per block outstanding). Both b's
// interleaved in one i-loop: W smem reads shared (half the LDS). Fused s0.
__global__ __launch_bounds__(NTH, 2) void k_uhat(const float* __restrict__ W) {
    __shared__ __align__(16) float stg[4][3584];  // per stage: ws[2560] + xs[1024]
    const int tid = threadIdx.x;
    const int n = tid >> 5;
    const int bp = tid & 31;
    const int b0 = 2 * bp;
    const int j0 = blockIdx.x * JB;

    const float* wsrc1 = W + (size_t)(tid >> 6) * IC * 256 + (tid & 63) * 4;
    const float* wsrc2 = W + (size_t)((tid + 320) >> 6) * IC * 256 + ((tid + 320) & 63) * 4;
    const unsigned wdst1 = (unsigned)__cvta_generic_to_shared(&stg[0][tid * 4]);
    const unsigned wdst2 = (unsigned)__cvta_generic_to_shared(&stg[0][(tid + 320) * 4]);
    const unsigned xdst = (unsigned)__cvta_generic_to_shared(&stg[0][2560 + tid * 4]);
    const unsigned sstride = 3584 * 4;

#define ISSUE(jv, sv)                                                          \
    do {                                                                       \
        CP16(wdst1 + (sv) * sstride, wsrc1 + (size_t)(jv) * 256);              \
        CP16(wdst2 + (sv) * sstride, wsrc2 + (size_t)(jv) * 256);              \
        if (tid < 256)                                                         \
            CP16(xdst + (sv) * sstride, g_xT + (size_t)(jv) * 1024 + tid * 4); \
    } while (0)

#pragma unroll
    for (int s = 0; s < 3; s++) { ISSUE(j0 + s, s); CP_COMMIT(); }

    unsigned long long s2a[8], s2b[8];
#pragma unroll
    for (int k = 0; k < 8; k++) { s2a[k] = 0ull; s2b[k] = 0ull; }

    for (int jj = 0; jj < JB; jj++) {
        CP_WAIT2();
        __syncthreads();

        const int cur = jj & 3;
        const float* ws = stg[cur];
        const float* xsm = ws + 2560;
        const ulonglong2* wb = (const ulonglong2*)(ws + n * 256);  // warp-uniform
        const int j = j0 + jj;

        unsigned long long u2a[8], u2b[8];
#pragma unroll
        for (int k = 0; k < 8; k++) { u2a[k] = 0ull; u2b[k] = 0ull; }
#pragma unroll
        for (int i = 0; i < ID; i++) {
            float2 xv = *(const float2*)(xsm + i * 64 + b0);  // LDS.64, 2-way
            unsigned long long xa2, xb2;
            asm("mov.b64 %0, {%1, %1};" : "=l"(xa2) : "f"(xv.x));
            asm("mov.b64 %0, {%1, %1};" : "=l"(xb2) : "f"(xv.y));
            ulonglong2 p0 = wb[i * 4 + 0], p1 = wb[i * 4 + 1];
            ulonglong2 p2 = wb[i * 4 + 2], p3 = wb[i * 4 + 3];
            FFMA2(u2a[0], xa2, p0.x); FFMA2(u2a[1], xa2, p0.y);
            FFMA2(u2a[2], xa2, p1.x); FFMA2(u2a[3], xa2, p1.y);
            FFMA2(u2a[4], xa2, p2.x); FFMA2(u2a[5], xa2, p2.y);
            FFMA2(u2a[6], xa2, p3.x); FFMA2(u2a[7], xa2, p3.y);
            FFMA2(u2b[0], xb2, p0.x); FFMA2(u2b[1], xb2, p0.y);
            FFMA2(u2b[2], xb2, p1.x); FFMA2(u2b[3], xb2, p1.y);
            FFMA2(u2b[4], xb2, p2.x); FFMA2(u2b[5], xb2, p2.y);
            FFMA2(u2b[6], xb2, p3.x); FFMA2(u2b[7], xb2, p3.y);
        }
        {
            __align__(16) __half2 ha[8], hb[8];
#pragma unroll
            for (int k = 0; k < 8; k++) {
                float lo, hi;
                asm("mov.b64 {%0, %1}, %2;" : "=f"(lo), "=f"(hi) : "l"(u2a[k]));
                ha[k] = __floats2half2_rn(lo, hi);
                asm("mov.b64 {%0, %1}, %2;" : "=f"(lo), "=f"(hi) : "l"(u2b[k]));
                hb[k] = __floats2half2_rn(lo, hi);
            }
            uint4* da = (uint4*)(g_uhat + ((size_t)(j * BB + b0) * NN + n) * OD);
            uint4* db = (uint4*)(g_uhat + ((size_t)(j * BB + b0 + 1) * NN + n) * OD);
            da[0] = *(uint4*)&ha[0]; da[1] = *(uint4*)&ha[4];
            db[0] = *(uint4*)&hb[0]; db[1] = *(uint4*)&hb[4];
#pragma unroll
            for (int k = 0; k < 8; k++) { FADD2(s2a[k], u2a[k]); FADD2(s2b[k], u2b[k]); }
        }

        if (jj + 3 < JB) ISSUE(j0 + jj + 3, (jj + 3) & 3);
        CP_COMMIT();
    }
#undef ISSUE

    float* spa = g_s0 + (b0 * NN + n) * OD;
    float* spb = g_s0 + ((b0 + 1) * NN + n) * OD;
#pragma unroll
    for (int k = 0; k < 8; k++) {
        float lo, hi;
        asm("mov.b64 {%0, %1}, %2;" : "=f"(lo), "=f"(hi) : "l"(s2a[k]));
        atomicAdd(spa + 2 * k, 0.1f * lo);
        atomicAdd(spa + 2 * k + 1, 0.1f * hi);
        asm("mov.b64 {%0, %1}, %2;" : "=f"(lo), "=f"(hi) : "l"(s2b[k]));
        atomicAdd(spb + 2 * k, 0.1f * lo);
        atomicAdd(spb + 2 * k + 1, 0.1f * hi);
    }
}

// squash scale for one 16-float s vector
__device__ __forceinline__ float squash_scale(const float* s) {
    float s2 = 0.f;
#pragma unroll
    for (int o = 0; o < OD; o++) s2 = fmaf(s[o], s[o], s2);
    return (s2 / (1.f + s2)) * rsqrtf(s2 + 1e-7f);
}

// ───────────────────────── Kernel C: routing pass ───────────────────────────
// Squash fused into the prologue: each thread squashes its own (b,n) s-vector
// from the previous pass buffer(s) -> no standalone squash kernels.
// pass=1: vs = squash(s0), accumulate s1. pass=2: vs = squash(s0)+squash(s1),
// accumulate s2.
__global__ __launch_bounds__(RT_TH, 3) void k_route(int pass) {
    const int tid = threadIdx.x;
    const int n = tid & 15;
    const int b = blockIdx.y * 16 + (tid >> 4);
    const bool act = (n < NN);
    const int j0 = blockIdx.x * RT_JB;
    const int row = (b * NN + (act ? n : 0)) * OD;

    __half2 vs2[8];
    {
        float vsf[OD];
        {
            const float4* p0 = (const float4*)(g_s0 + row);
            float s0[OD];
#pragma unroll
            for (int k = 0; k < 4; k++) {
                float4 v = p0[k];
                s0[4 * k] = v.x; s0[4 * k + 1] = v.y;
                s0[4 * k + 2] = v.z; s0[4 * k + 3] = v.w;
            }
            float sc0 = squash_scale(s0);
#pragma unroll
            for (int o = 0; o < OD; o++) vsf[o] = sc0 * s0[o];
        }
        if (pass == 2) {
            const float4* p1 = (const float4*)(g_s1 + row);
            float s1[OD];
#pragma unroll
            for (int k = 0; k < 4; k++) {
                float4 v = p1[k];
                s1[4 * k] = v.x; s1[4 * k + 1] = v.y;
                s1[4 * k + 2] = v.z; s1[4 * k + 3] = v.w;
            }
            float sc1 = squash_scale(s1);
#pragma unroll
            for (int o = 0; o < OD; o++) vsf[o] = fmaf(sc1, s1[o], vsf[o]);
        }
#pragma unroll
        for (int k = 0; k < 8; k++)
            vs2[k] = __floats2half2_rn(vsf[2 * k], vsf[2 * k + 1]);
    }

    float s_acc[OD];
#pragma unroll
    for (int o = 0; o < OD; o++) s_acc[o] = 0.f;

    const uint4* up = (const uint4*)(g_uhat + ((size_t)(j0 * BB + b) * NN + n) * OD);
    const size_t step = (BB * NN * OD) / 8;

    uint4 pA0 = make_uint4(0, 0, 0, 0), pB0 = pA0, pA1 = pA0, pB1 = pA0;
    if (act) { pA0 = up[0]; pB0 = up[1]; pA1 = up[step]; pB1 = up[step + 1]; }

    for (int jo = 0; jo < RT_JB; jo += 2) {
        uint4 cA0 = pA0, cB0 = pB0, cA1 = pA1, cB1 = pB1;
        if (jo + 2 < RT_JB && act) {
            const uint4* nx = up + (size_t)(jo + 2) * step;
            pA0 = nx[0]; pB0 = nx[1];
            pA1 = nx[step]; pB1 = nx[step + 1];
        }
        const __half2* h0 = (const __half2*)&cA0;
        const __half2* g0 = (const __half2*)&cB0;
        const __half2* h1 = (const __half2*)&cA1;
        const __half2* g1 = (const __half2*)&cB1;

        __half2 dA0 = __hmul2(h0[0], vs2[0]), dB0 = __hmul2(g0[0], vs2[4]);
        __half2 dA1 = __hmul2(h1[0], vs2[0]), dB1 = __hmul2(g1[0], vs2[4]);
#pragma unroll
        for (int k = 1; k < 4; k++) {
            dA0 = __hfma2(h0[k], vs2[k], dA0); dB0 = __hfma2(g0[k], vs2[4 + k], dB0);
            dA1 = __hfma2(h1[k], vs2[k], dA1); dB1 = __hfma2(g1[k], vs2[4 + k], dB1);
        }
        __half2 ds0 = __hadd2(dA0, dB0), ds1 = __hadd2(dA1, dB1);
        float d0 = __low2float(ds0) + __high2float(ds0);
        float d1 = __low2float(ds1) + __high2float(ds1);

        float e0 = act ? __expf(d0) : 0.f;
        float e1 = act ? __expf(d1) : 0.f;
        float s0 = e0, s1 = e1;
#pragma unroll
        for (int m = 1; m < 16; m <<= 1) {
            s0 += __shfl_xor_sync(0xFFFFFFFFu, s0, m, 16);
            s1 += __shfl_xor_sync(0xFFFFFFFFu, s1, m, 16);
        }
        float c0 = __fdividef(e0, s0);
        float c1 = __fdividef(e1, s1);

#pragma unroll
        for (int k = 0; k < 4; k++) {
            float2 f = __half22float2(h0[k]);
            s_acc[2 * k] = fmaf(c0, f.x, s_acc[2 * k]);
            s_acc[2 * k + 1] = fmaf(c0, f.y, s_acc[2 * k + 1]);
            f = __half22float2(g0[k]);
            s_acc[8 + 2 * k] = fmaf(c0, f.x, s_acc[8 + 2 * k]);
            s_acc[9 + 2 * k] = fmaf(c0, f.y, s_acc[9 + 2 * k]);
            f = __half22float2(h1[k]);
            s_acc[2 * k] = fmaf(c1, f.x, s_acc[2 * k]);
            s_acc[2 * k + 1] = fmaf(c1, f.y, s_acc[2 * k + 1]);
            f = __half22float2(g1[k]);
            s_acc[8 + 2 * k] = fmaf(c1, f.x, s_acc[8 + 2 * k]);
            s_acc[9 + 2 * k] = fmaf(c1, f.y, s_acc[9 + 2 * k]);
        }
    }

    if (act) {
        float* sp = ((pass == 1) ? g_s1 : g_s2) + (b * NN + n) * OD;
#pragma unroll
        for (int o = 0; o < OD; o++) atomicAdd(sp + o, s_acc[o]);
    }
}

// ─────────────────── Final: v2 = squash(s2) -> output ───────────────────────
__global__ void k_squash_out(float* __restrict__ out) {
    int t = threadIdx.x;
    if (t >= BB * NN) return;
    const float4* sp = (const float4*)(g_s2 + t * OD);
    float4 a = sp[0], b4 = sp[1], c4 = sp[2], d4 = sp[3];
    float s[OD] = {a.x, a.y, a.z, a.w, b4.x, b4.y, b4.z, b4.w,
                   c4.x, c4.y, c4.z, c4.w, d4.x, d4.y, d4.z, d4.w};
    float sc = squash_scale(s);
    float4* op = (float4*)(out + t * OD);
    op[0] = make_float4(sc * s[0], sc * s[1], sc * s[2], sc * s[3]);
    op[1] = make_float4(sc * s[4], sc * s[5], sc * s[6], sc * s[7]);
    op[2] = make_float4(sc * s[8], sc * s[9], sc * s[10], sc * s[11]);
    op[3] = make_float4(sc * s[12], sc * s[13], sc * s[14], sc * s[15]);
}

extern "C" void kernel_launch(void* const* d_in, const int* in_sizes, int n_in,
                              void* d_out, int out_size) {
    const float* x = (const float*)d_in[0];  // [64, 6912, 16]
    const float* W = (const float*)d_in[1];  // [10, 6912, 16, 16]
    float* out = (float*)d_out;              // [64, 10, 16]

    dim3 rgrid(IC / RT_JB, BB / 16);  // (216, 4)

    k_nop<<<1, 32>>>();  // 4 shims: k_uhat becomes the 6th launch (ncu -s 5 -c 1)
    k_nop<<<1, 32>>>();
    k_nop<<<1, 32>>>();
    k_nop<<<1, 32>>>();
    k_xt<<<IC / JT, 256>>>(x);        // xT + zero s buffers
    k_uhat<<<IC / JB, NTH>>>(W);      // u_hat (fp16) + fused s0
    k_route<<<rgrid, RT_TH>>>(1);     // squash(s0) in prologue; emit s1
    k_route<<<rgrid, RT_TH>>>(2);     // squash(s0)+squash(s1); emit s2
    k_squash_out<<<1, 640>>>(out);    // v2 -> output
}

// round 8
// speedup vs baseline: 1.3937x; 1.0729x over previous
#include <cuda_runtime.h>
#include <cuda_fp16.h>
#include <math.h>

#define BB 64
#define NN 10
#define ID 16
#define OD 16
#define IC 6912
#define JB 24          // j-tile for k_uhat (grid 288, 2 blocks/SM)
#define NTH 320        // k_uhat: warp = n; lane owns b-pair
#define JT 16          // j's per k_xt block
#define RT_JB 48       // j-tile for k_route (grid 144 x 4)
#define RT_TH 256      // k_route: 16-lane groups, n = tid&15

// Packed f32x2 helpers (sm_100+ PTX)
#define FFMA2(d, a, b) asm("fma.rn.f32x2 %0, %1, %2, %0;" : "+l"(d) : "l"(a), "l"(b))
#define FADD2(d, a)    asm("add.rn.f32x2 %0, %0, %1;"     : "+l"(d) : "l"(a))
// cp.async (LDGSTS)
#define CP16(dst, src) asm volatile("cp.async.ca.shared.global [%0], [%1], 16;" \
                                    :: "r"(dst), "l"(src))
#define CP_COMMIT()    asm volatile("cp.async.commit_group;")
#define CP_WAIT2()     asm volatile("cp.async.wait_group 2;")
#define CP_WAIT6()     asm volatile("cp.async.wait_group 6;")

// Scratch (device globals: allocation-free). u_hat fp16 [j][b][n][o].
__device__ __half g_uhat[(size_t)IC * BB * NN * OD + 128];
__device__ float g_xT[(size_t)IC * ID * BB];  // x transposed: [j][i][b]
__device__ float g_s0[BB * NN * OD];          // s from pass 0 (uhat epilogue)
__device__ float g_s1[BB * NN * OD];          // s from pass 1 (route 1)
__device__ float g_s2[BB * NN * OD];          // s from pass 2 (route 2)

// ─────────── Kernel T: transpose x -> xT [j][i][b]; also zero g_s* ──────────
__global__ void k_xt(const float* __restrict__ x) {
    __shared__ float t[ID][66];
    const int tid = threadIdx.x;  // 256
    const int bid = blockIdx.x;
    if (bid < 30) {  // zero 3 x 10240 floats of s buffers
        float* z = (bid < 10) ? g_s0 : (bid < 20) ? g_s1 : g_s2;
        int off = (bid % 10) * 1024;
#pragma unroll
        for (int r = 0; r < 4; r++) z[off + r * 256 + tid] = 0.f;
    }
    const int jb = bid * JT;
    for (int jj = 0; jj < JT; jj++) {
        const int j = jb + jj;
#pragma unroll
        for (int r = 0; r < 4; r++) {
            int e = r * 256 + tid;
            t[e & 15][e >> 4] = x[((size_t)(e >> 4) * IC + j) * 16 + (e & 15)];
        }
        __syncthreads();
#pragma unroll
        for (int r = 0; r < 4; r++) {
            int o = r * 256 + tid;
            g_xT[(size_t)j * (ID * BB) + o] = t[o >> 6][o & 63];
        }
        __syncthreads();
    }
}

// ───────────────────────────── Kernel A: u_hat GEMM ─────────────────────────
// BARRIER-FREE: each warp (= one n) owns a private 4-stage cp.async ring for
// its 1 KB W slice; only __syncwarp per j. x read via coalesced LDG (L1 hits
// for 9/10 warps). f32x2 FMA; fused s0 (c = 0.1).
__global__ __launch_bounds__(NTH, 2) void k_uhat(const float* __restrict__ W) {
    __shared__ __align__(16) float ws[NN][4][256];  // [warp][stage] 40 KB
    const int tid = threadIdx.x;
    const int w = tid >> 5;       // warp = n
    const int lane = tid & 31;
    const int b0 = 2 * lane;
    const int j0 = blockIdx.x * JB;

    const float* wsrc = W + (size_t)w * IC * 256;  // + j*256
    const unsigned sb = (unsigned)__cvta_generic_to_shared(&ws[w][0][0]);
    const unsigned d1 = sb + lane * 16;
    const unsigned d2 = sb + (lane + 32) * 16;

#define WISSUE(jv, sv)                                      \
    do {                                                    \
        const float* s_ = wsrc + (size_t)(jv) * 256;        \
        CP16(d1 + (sv) * 1024, s_ + lane * 4);              \
        CP16(d2 + (sv) * 1024, s_ + lane * 4 + 128);        \
    } while (0)

#pragma unroll
    for (int s = 0; s < 3; s++) { WISSUE(j0 + s, s); CP_COMMIT(); }

    unsigned long long s2a[8], s2b[8];
#pragma unroll
    for (int k = 0; k < 8; k++) { s2a[k] = 0ull; s2b[k] = 0ull; }

    for (int jj = 0; jj < JB; jj++) {
        CP_WAIT2();
        __syncwarp();  // warp-local: other lanes' copies of this stage visible

        const int j = j0 + jj;
        const ulonglong2* wb = (const ulonglong2*)&ws[w][jj & 3][0];  // uniform
        const float* xj = g_xT + (size_t)j * 1024 + b0;

        unsigned long long u2a[8], u2b[8];
#pragma unroll
        for (int k = 0; k < 8; k++) { u2a[k] = 0ull; u2b[k] = 0ull; }

        float2 xa[4];
#pragma unroll
        for (int k = 0; k < 4; k++) xa[k] = *(const float2*)(xj + k * 64);
#pragma unroll
        for (int it = 0; it < 4; it++) {  // 4 i's per chunk
            float2 xb[4];
            if (it < 3) {
#pragma unroll
                for (int k = 0; k < 4; k++)
                    xb[k] = *(const float2*)(xj + (4 * (it + 1) + k) * 64);
            }
#pragma unroll
            for (int k = 0; k < 4; k++) {
                const int i = 4 * it + k;
                unsigned long long xa2, xb2;
                asm("mov.b64 %0, {%1, %1};" : "=l"(xa2) : "f"(xa[k].x));
                asm("mov.b64 %0, {%1, %1};" : "=l"(xb2) : "f"(xa[k].y));
                ulonglong2 p0 = wb[i * 4 + 0], p1 = wb[i * 4 + 1];
                ulonglong2 p2 = wb[i * 4 + 2], p3 = wb[i * 4 + 3];
                FFMA2(u2a[0], xa2, p0.x); FFMA2(u2a[1], xa2, p0.y);
                FFMA2(u2a[2], xa2, p1.x); FFMA2(u2a[3], xa2, p1.y);
                FFMA2(u2a[4], xa2, p2.x); FFMA2(u2a[5], xa2, p2.y);
                FFMA2(u2a[6], xa2, p3.x); FFMA2(u2a[7], xa2, p3.y);
                FFMA2(u2b[0], xb2, p0.x); FFMA2(u2b[1], xb2, p0.y);
                FFMA2(u2b[2], xb2, p1.x); FFMA2(u2b[3], xb2, p1.y);
                FFMA2(u2b[4], xb2, p2.x); FFMA2(u2b[5], xb2, p2.y);
                FFMA2(u2b[6], xb2, p3.x); FFMA2(u2b[7], xb2, p3.y);
            }
#pragma unroll
            for (int k = 0; k < 4; k++) xa[k] = xb[k];
        }
        {
            __align__(16) __half2 ha[8], hb[8];
#pragma unroll
            for (int k = 0; k < 8; k++) {
                float lo, hi;
                asm("mov.b64 {%0, %1}, %2;" : "=f"(lo), "=f"(hi) : "l"(u2a[k]));
                ha[k] = __floats2half2_rn(lo, hi);
                asm("mov.b64 {%0, %1}, %2;" : "=f"(lo), "=f"(hi) : "l"(u2b[k]));
                hb[k] = __floats2half2_rn(lo, hi);
            }
            uint4* da = (uint4*)(g_uhat + ((size_t)(j * BB + b0) * NN + w) * OD);
            uint4* db = (uint4*)(g_uhat + ((size_t)(j * BB + b0 + 1) * NN + w) * OD);
            da[0] = *(uint4*)&ha[0]; da[1] = *(uint4*)&ha[4];
            db[0] = *(uint4*)&hb[0]; db[1] = *(uint4*)&hb[4];
#pragma unroll
            for (int k = 0; k < 8; k++) { FADD2(s2a[k], u2a[k]); FADD2(s2b[k], u2b[k]); }
        }
        if (jj + 3 < JB) WISSUE(j0 + jj + 3, (jj + 3) & 3);
        CP_COMMIT();
    }
#undef WISSUE

    float* spa = g_s0 + (b0 * NN + w) * OD;
    float* spb = g_s0 + ((b0 + 1) * NN + w) * OD;
#pragma unroll
    for (int k = 0; k < 8; k++) {
        float lo, hi;
        asm("mov.b64 {%0, %1}, %2;" : "=f"(lo), "=f"(hi) : "l"(s2a[k]));
        atomicAdd(spa + 2 * k, 0.1f * lo);
        atomicAdd(spa + 2 * k + 1, 0.1f * hi);
        asm("mov.b64 {%0, %1}, %2;" : "=f"(lo), "=f"(hi) : "l"(s2b[k]));
        atomicAdd(spb + 2 * k, 0.1f * lo);
        atomicAdd(spb + 2 * k + 1, 0.1f * hi);
    }
}

// squash scale for one 16-float s vector
__device__ __forceinline__ float squash_scale(const float* s) {
    float s2 = 0.f;
#pragma unroll
    for (int o = 0; o < OD; o++) s2 = fmaf(s[o], s[o], s2);
    return (s2 / (1.f + s2)) * rsqrtf(s2 + 1e-7f);
}

// ───────────────────────── Kernel C: routing pass ───────────────────────────
// 8-stage cp.async smem pipeline (7 stages / 36 KB in flight) feeds the j-loop
// from smem (29 cyc) instead of DRAM. One 8-warp barrier per j. Fused squash
// prologue. pass=1: vs=squash(s0); pass=2: vs=squash(s0)+squash(s1).
__global__ __launch_bounds__(RT_TH, 3) void k_route(int pass) {
    __shared__ __align__(16) char tile[8][5376];  // per j: 16 b x 336 B (pad)
    const int tid = threadIdx.x;
    const int n = tid & 15;
    const int bg = tid >> 4;
    const int b = blockIdx.y * 16 + bg;
    const bool act = (n < NN);
    const int j0 = blockIdx.x * RT_JB;

    // copy plan: 320 x 16B chunks per j; thread handles chunks tid, tid+256
    const int c0 = tid, c1 = tid + 256;
    const bool has1 = (c1 < 320);
    const unsigned tb = (unsigned)__cvta_generic_to_shared(&tile[0][0]);
    const unsigned dst0 = tb + (c0 / 20) * 336 + (c0 % 20) * 16;
    const unsigned dst1 = tb + (c1 / 20) * 336 + (c1 % 20) * 16;
    const char* gbase = (const char*)g_uhat +
                        (size_t)(j0 * BB + blockIdx.y * 16) * 320;

#define RISSUE(jv, sv)                                              \
    do {                                                            \
        const char* s_ = gbase + (size_t)(jv) * (BB * 320);         \
        CP16(dst0 + (sv) * 5376, s_ + c0 * 16);                     \
        if (has1) CP16(dst1 + (sv) * 5376, s_ + c1 * 16);           \
    } while (0)

#pragma unroll
    for (int s = 0; s < 7; s++) { RISSUE(s, s); CP_COMMIT(); }

    // fused squash prologue -> vs (fp16 pairs)
    __half2 vs2[8];
    {
        const int row = (b * NN + (act ? n : 0)) * OD;
        float vsf[OD];
        {
            const float4* p0 = (const float4*)(g_s0 + row);
            float sv[OD];
#pragma unroll
            for (int k = 0; k < 4; k++) {
                float4 v = p0[k];
                sv[4 * k] = v.x; sv[4 * k + 1] = v.y;
                sv[4 * k + 2] = v.z; sv[4 * k + 3] = v.w;
            }
            float sc = squash_scale(sv);
#pragma unroll
            for (int o = 0; o < OD; o++) vsf[o] = sc * sv[o];
        }
        if (pass == 2) {
            const float4* p1 = (const float4*)(g_s1 + row);
            float sv[OD];
#pragma unroll
            for (int k = 0; k < 4; k++) {
                float4 v = p1[k];
                sv[4 * k] = v.x; sv[4 * k + 1] = v.y;
                sv[4 * k + 2] = v.z; sv[4 * k + 3] = v.w;
            }
            float sc = squash_scale(sv);
#pragma unroll
            for (int o = 0; o < OD; o++) vsf[o] = fmaf(sc, sv[o], vsf[o]);
        }
#pragma unroll
        for (int k = 0; k < 8; k++)
            vs2[k] = __floats2half2_rn(vsf[2 * k], vsf[2 * k + 1]);
    }

    float s_acc[OD];
#pragma unroll
    for (int o = 0; o < OD; o++) s_acc[o] = 0.f;

    for (int jj = 0; jj < RT_JB; jj++) {
        CP_WAIT6();
        __syncthreads();  // stage jj&7 visible to all; prior stage reads done

        uint4 cA = make_uint4(0, 0, 0, 0), cB = cA;
        if (act) {
            const char* tp = tile[jj & 7] + bg * 336 + n * 32;
            cA = *(const uint4*)tp;
            cB = *(const uint4*)(tp + 16);
        }
        const __half2* hA = (const __half2*)&cA;
        const __half2* hB = (const __half2*)&cB;

        __half2 dA = __hmul2(hA[0], vs2[0]), dB = __hmul2(hB[0], vs2[4]);
#pragma unroll
        for (int k = 1; k < 4; k++) {
            dA = __hfma2(hA[k], vs2[k], dA);
            dB = __hfma2(hB[k], vs2[4 + k], dB);
        }
        __half2 ds = __hadd2(dA, dB);
        float d = __low2float(ds) + __high2float(ds);

        float e = act ? __expf(d) : 0.f;
        float sum = e;
#pragma unroll
        for (int m = 1; m < 16; m <<= 1)
            sum += __shfl_xor_sync(0xFFFFFFFFu, sum, m, 16);
        float c = __fdividef(e, sum);

#pragma unroll
        for (int k = 0; k < 4; k++) {
            float2 f = __half22float2(hA[k]);
            s_acc[2 * k] = fmaf(c, f.x, s_acc[2 * k]);
            s_acc[2 * k + 1] = fmaf(c, f.y, s_acc[2 * k + 1]);
            f = __half22float2(hB[k]);
            s_acc[8 + 2 * k] = fmaf(c, f.x, s_acc[8 + 2 * k]);
            s_acc[9 + 2 * k] = fmaf(c, f.y, s_acc[9 + 2 * k]);
        }

        if (jj + 7 < RT_JB) RISSUE(jj + 7, (jj + 7) & 7);
        CP_COMMIT();
    }
#undef RISSUE

    if (act) {
        float* sp = ((pass == 1) ? g_s1 : g_s2) + (b * NN + n) * OD;
#pragma unroll
        for (int o = 0; o < OD; o++) atomicAdd(sp + o, s_acc[o]);
    }
}

// ─────────────────── Final: v2 = squash(s2) -> output ───────────────────────
__global__ void k_squash_out(float* __restrict__ out) {
    int t = threadIdx.x;
    if (t >= BB * NN) return;
    const float4* sp = (const float4*)(g_s2 + t * OD);
    float4 a = sp[0], b4 = sp[1], c4 = sp[2], d4 = sp[3];
    float s[OD] = {a.x, a.y, a.z, a.w, b4.x, b4.y, b4.z, b4.w,
                   c4.x, c4.y, c4.z, c4.w, d4.x, d4.y, d4.z, d4.w};
    float sc = squash_scale(s);
    float4* op = (float4*)(out + t * OD);
    op[0] = make_float4(sc * s[0], sc * s[1], sc * s[2], sc * s[3]);
    op[1] = make_float4(sc * s[4], sc * s[5], sc * s[6], sc * s[7]);
    op[2] = make_float4(sc * s[8], sc * s[9], sc * s[10], sc * s[11]);
    op[3] = make_float4(sc * s[12], sc * s[13], sc * s[14], sc * s[15]);
}

extern "C" void kernel_launch(void* const* d_in, const int* in_sizes, int n_in,
                              void* d_out, int out_size) {
    const float* x = (const float*)d_in[0];  // [64, 6912, 16]
    const float* W = (const float*)d_in[1];  // [10, 6912, 16, 16]
    float* out = (float*)d_out;              // [64, 10, 16]

    dim3 rgrid(IC / RT_JB, BB / 16);  // (144, 4)

    k_xt<<<IC / JT, 256>>>(x);        // xT + zero s buffers
    k_uhat<<<IC / JB, NTH>>>(W);      // u_hat (fp16) + fused s0
    k_route<<<rgrid, RT_TH>>>(1);     // squash(s0) in prologue; emit s1
    k_route<<<rgrid, RT_TH>>>(2);     // squash(s0)+squash(s1); emit s2
    k_squash_out<<<1, 640>>>(out);    // v2 -> output
}

// round 9
// speedup vs baseline: 1.7156x; 1.2310x over previous
#include <cuda_runtime.h>
#include <cuda_fp16.h>
#include <math.h>

#define BB 64
#define NN 10
#define ID 16
#define OD 16
#define IC 6912
#define JB 24          // j-tile for k_uhat (grid 288, 2 blocks/SM)
#define NTH 320        // k_uhat: warp = n; lane owns b = 2lane, 2lane+1
#define JT 16          // j's per k_xt block
#define RT_TH 256      // k_route: 16-lane groups, n = tid&15
#define RT_BLOCKS 444  // persistent: 148 SMs x 3
#define UHAT_SMEM (40960 + 40960)  // W rings + out staging

// Packed f32x2 helpers (sm_100+ PTX)
#define FFMA2(d, a, b) asm("fma.rn.f32x2 %0, %1, %2, %0;" : "+l"(d) : "l"(a), "l"(b))
#define FADD2(d, a)    asm("add.rn.f32x2 %0, %0, %1;"     : "+l"(d) : "l"(a))
// cp.async (LDGSTS)
#define CP16(dst, src) asm volatile("cp.async.ca.shared.global [%0], [%1], 16;" \
                                    :: "r"(dst), "l"(src))
#define CP_COMMIT()    asm volatile("cp.async.commit_group;")
#define CP_WAIT2()     asm volatile("cp.async.wait_group 2;")
#define CP_WAIT6()     asm volatile("cp.async.wait_group 6;")
// bulk shared->global store (separate group machinery from cp.async)
#define BULK_ST(gdst, ssrc, bytes)                                             \
    asm volatile("cp.async.bulk.global.shared::cta.bulk_group [%0], [%1], %2;" \
                 :: "l"(gdst), "r"(ssrc), "r"(bytes) : "memory")
#define BULK_COMMIT()  asm volatile("cp.async.bulk.commit_group;")
#define BULK_WAIT_RD1() asm volatile("cp.async.bulk.wait_group.read 1;")
#define BULK_WAIT0()   asm volatile("cp.async.bulk.wait_group 0;")
#define FENCE_ASYNC()  asm volatile("fence.proxy.async.shared::cta;" ::: "memory")

// Scratch (device globals: allocation-free). u_hat fp16, layout [j][n][b][o].
__device__ __half g_uhat[(size_t)IC * NN * BB * OD];
__device__ __half g_xh[(size_t)IC * ID * BB];  // x fp16, [j][i][b]
__device__ float g_s0[BB * NN * OD];           // s from pass 0
__device__ float g_s1[BB * NN * OD];           // s from pass 1
__device__ float g_s2[BB * NN * OD];           // s from pass 2

// ───── Kernel T: x [b][j][i] fp32 -> g_xh [j][i][b] fp16; also zero g_s* ────
__global__ void k_xt(const float* __restrict__ x) {
    __shared__ __half th[ID][BB];
    const int tid = threadIdx.x;  // 256
    const int bid = blockIdx.x;
    if (bid < 30) {
        float* z = (bid < 10) ? g_s0 : (bid < 20) ? g_s1 : g_s2;
        int off = (bid % 10) * 1024;
#pragma unroll
        for (int r = 0; r < 4; r++) z[off + r * 256 + tid] = 0.f;
    }
    const int jb = bid * JT;
    for (int jj = 0; jj < JT; jj++) {
        const int j = jb + jj;
#pragma unroll
        for (int r = 0; r < 4; r++) {
            int e = r * 256 + tid;  // b = e>>4, i = e&15
            th[e & 15][e >> 4] =
                __float2half(x[((size_t)(e >> 4) * IC + j) * 16 + (e & 15)]);
        }
        __syncthreads();
#pragma unroll
        for (int r = 0; r < 2; r++) {
            int c = r * 256 + tid;          // u32 index: i = c>>5, b = (c&31)*2
            __half2 p = __halves2half2(th[c >> 5][(c & 31) * 2],
                                       th[c >> 5][(c & 31) * 2 + 1]);
            ((unsigned*)g_xh)[(size_t)j * 512 + c] = *(unsigned*)&p;
        }
        __syncthreads();
    }
}

// ───────────────────────────── Kernel A: u_hat GEMM ─────────────────────────
// W: per-warp 4-stage CP16 ring (warp-local syncs only). x: fp16, 16 coalesced
// LDG.32 per j (both b's per load). OUT: staged in smem, emitted as one
// 2KB cp.async.bulk per (j, n) -> perfectly coalesced, no STG scatter.
__global__ __launch_bounds__(NTH, 2) void k_uhat(const float* __restrict__ W) {
    extern __shared__ __align__(16) char dsm[];
    float* wsf = (float*)dsm;            // [10 warps][4 stages][256 f] = 40960B
    char* outs = dsm + 40960;            // [2 slots][10 n][2048B]     = 40960B
    const int tid = threadIdx.x;
    const int w = tid >> 5;       // warp = n
    const int lane = tid & 31;
    const int j0 = blockIdx.x * JB;

    const float* wsrc = W + (size_t)w * IC * 256;
    const unsigned wb_sh = (unsigned)__cvta_generic_to_shared(wsf + w * 1024);
    const unsigned d1 = wb_sh + lane * 16;
    const unsigned d2 = wb_sh + 512 + lane * 16;

#define WISSUE(jv, sv)                                   \
    do {                                                 \
        const float* s_ = wsrc + (size_t)(jv) * 256;     \
        CP16(d1 + (sv) * 1024, s_ + lane * 4);           \
        CP16(d2 + (sv) * 1024, s_ + lane * 4 + 128);     \
    } while (0)

#pragma unroll
    for (int s = 0; s < 3; s++) { WISSUE(j0 + s, s); CP_COMMIT(); }

    const unsigned outsh_base = (unsigned)__cvta_generic_to_shared(outs) +
                                w * 2048 + lane * 64;

    unsigned long long s2a[8], s2b[8];
#pragma unroll
    for (int k = 0; k < 8; k++) { s2a[k] = 0ull; s2b[k] = 0ull; }

    for (int jj = 0; jj < JB; jj++) {
        const int j = j0 + jj;
        // issue x loads first (latency overlaps the W-ring wait)
        const unsigned* xp = (const unsigned*)g_xh + (size_t)j * 512;
        unsigned x32[16];
#pragma unroll
        for (int i = 0; i < ID; i++) x32[i] = xp[i * 32 + lane];

        CP_WAIT2();
        __syncwarp();

        const ulonglong2* wb = (const ulonglong2*)(wsf + (w * 4 + (jj & 3)) * 256);

        unsigned long long u2a[8], u2b[8];
#pragma unroll
        for (int k = 0; k < 8; k++) { u2a[k] = 0ull; u2b[k] = 0ull; }
#pragma unroll
        for (int i = 0; i < ID; i++) {
            float2 fx = __half22float2(*(__half2*)&x32[i]);  // b=2lane, 2lane+1
            unsigned long long xa2, xb2;
            asm("mov.b64 %0, {%1, %1};" : "=l"(xa2) : "f"(fx.x));
            asm("mov.b64 %0, {%1, %1};" : "=l"(xb2) : "f"(fx.y));
            ulonglong2 p0 = wb[i * 4 + 0], p1 = wb[i * 4 + 1];
            ulonglong2 p2 = wb[i * 4 + 2], p3 = wb[i * 4 + 3];
            FFMA2(u2a[0], xa2, p0.x); FFMA2(u2a[1], xa2, p0.y);
            FFMA2(u2a[2], xa2, p1.x); FFMA2(u2a[3], xa2, p1.y);
            FFMA2(u2a[4], xa2, p2.x); FFMA2(u2a[5], xa2, p2.y);
            FFMA2(u2a[6], xa2, p3.x); FFMA2(u2a[7], xa2, p3.y);
            FFMA2(u2b[0], xb2, p0.x); FFMA2(u2b[1], xb2, p0.y);
            FFMA2(u2b[2], xb2, p1.x); FFMA2(u2b[3], xb2, p1.y);
            FFMA2(u2b[4], xb2, p2.x); FFMA2(u2b[5], xb2, p2.y);
            FFMA2(u2b[6], xb2, p3.x); FFMA2(u2b[7], xb2, p3.y);
        }

        // convert + stage to smem + bulk store (slot jj&1)
        {
            __align__(16) __half2 ha[8], hb[8];
#pragma unroll
            for (int k = 0; k < 8; k++) {
                float lo, hi;
                asm("mov.b64 {%0, %1}, %2;" : "=f"(lo), "=f"(hi) : "l"(u2a[k]));
                ha[k] = __floats2half2_rn(lo, hi);
                asm("mov.b64 {%0, %1}, %2;" : "=f"(lo), "=f"(hi) : "l"(u2b[k]));
                hb[k] = __floats2half2_rn(lo, hi);
            }
            if (lane == 0) BULK_WAIT_RD1();  // slot's bulk from jj-2 done reading
            __syncwarp();
            const unsigned ob = outsh_base + (jj & 1) * 20480;
            asm volatile("st.shared.v4.b32 [%0], {%1,%2,%3,%4};" :: "r"(ob),
                "r"(*(unsigned*)&ha[0]), "r"(*(unsigned*)&ha[1]),
                "r"(*(unsigned*)&ha[2]), "r"(*(unsigned*)&ha[3]));
            asm volatile("st.shared.v4.b32 [%0], {%1,%2,%3,%4};" :: "r"(ob + 16),
                "r"(*(unsigned*)&ha[4]), "r"(*(unsigned*)&ha[5]),
                "r"(*(unsigned*)&ha[6]), "r"(*(unsigned*)&ha[7]));
            asm volatile("st.shared.v4.b32 [%0], {%1,%2,%3,%4};" :: "r"(ob + 32),
                "r"(*(unsigned*)&hb[0]), "r"(*(unsigned*)&hb[1]),
                "r"(*(unsigned*)&hb[2]), "r"(*(unsigned*)&hb[3]));
            asm volatile("st.shared.v4.b32 [%0], {%1,%2,%3,%4};" :: "r"(ob + 48),
                "r"(*(unsigned*)&hb[4]), "r"(*(unsigned*)&hb[5]),
                "r"(*(unsigned*)&hb[6]), "r"(*(unsigned*)&hb[7]));
            __syncwarp();
            if (lane == 0) {
                FENCE_ASYNC();
                const char* gdst = (const char*)g_uhat + ((size_t)j * NN + w) * 2048;
                unsigned ssrc = (unsigned)__cvta_generic_to_shared(outs) +
                                (jj & 1) * 20480 + w * 2048;
                BULK_ST(gdst, ssrc, 2048);
                BULK_COMMIT();
            }
#pragma unroll
            for (int k = 0; k < 8; k++) { FADD2(s2a[k], u2a[k]); FADD2(s2b[k], u2b[k]); }
        }

        if (jj + 3 < JB) WISSUE(j0 + jj + 3, (jj + 3) & 3);
        CP_COMMIT();
    }
#undef WISSUE
    if (lane == 0) BULK_WAIT0();  // flush stores

    const int b0 = 2 * lane;
    float* spa = g_s0 + (b0 * NN + w) * OD;
    float* spb = g_s0 + ((b0 + 1) * NN + w) * OD;
#pragma unroll
    for (int k = 0; k < 8; k++) {
        float lo, hi;
        asm("mov.b64 {%0, %1}, %2;" : "=f"(lo), "=f"(hi) : "l"(s2a[k]));
        atomicAdd(spa + 2 * k, 0.1f * lo);
        atomicAdd(spa + 2 * k + 1, 0.1f * hi);
        asm("mov.b64 {%0, %1}, %2;" : "=f"(lo), "=f"(hi) : "l"(s2b[k]));
        atomicAdd(spb + 2 * k, 0.1f * lo);
        atomicAdd(spb + 2 * k + 1, 0.1f * hi);
    }
}

// squash scale for one 16-float s vector
__device__ __forceinline__ float squash_scale(const float* s) {
    float s2 = 0.f;
#pragma unroll
    for (int o = 0; o < OD; o++) s2 = fmaf(s[o], s[o], s2);
    return (s2 / (1.f + s2)) * rsqrtf(s2 + 1e-7f);
}

// ───────────────────── Kernel C: PERSISTENT routing pass ────────────────────
// Grid 444 = 148 SMs x 3: no wave-quantization tail. Block bid: bgrp = bid&3,
// j-range = contiguous slice of IC (balance +-1 j). 8-stage CP16 smem ring.
__global__ __launch_bounds__(RT_TH, 3) void k_route(int pass) {
    __shared__ __align__(16) char tile[8][5376];  // per j: 16 b x 336 B (pad)
    const int tid = threadIdx.x;
    const int n = tid & 15;
    const int bg = tid >> 4;
    const int bgrp = blockIdx.x & 3;
    const int idx = blockIdx.x >> 2;                  // 0..110
    const int jbeg = (idx * IC) / 111;
    const int jend = ((idx + 1) * IC) / 111;
    const int njs = jend - jbeg;
    const int b = bgrp * 16 + bg;
    const bool act = (n < NN);

    // copy plan: 320 x 16B chunks/j; layout [j][n][b][o] -> 2048B per (j,n)
    const int c0 = tid, c1 = tid + 256;
    const bool has1 = (c1 < 320);
    const unsigned tb = (unsigned)__cvta_generic_to_shared(&tile[0][0]);
    const int n0 = c0 >> 5, t0 = c0 & 31, bg0 = t0 >> 1, hf0 = t0 & 1;
    const int n1 = c1 >> 5, t1 = c1 & 31, bg1 = t1 >> 1, hf1 = t1 & 1;
    const unsigned dst0 = tb + bg0 * 336 + n0 * 32 + hf0 * 16;
    const unsigned dst1 = tb + bg1 * 336 + n1 * 32 + hf1 * 16;
    const size_t so0 = (size_t)n0 * 2048 + (bgrp * 16 + bg0) * 32 + hf0 * 16;
    const size_t so1 = (size_t)n1 * 2048 + (bgrp * 16 + bg1) * 32 + hf1 * 16;
    const char* gu = (const char*)g_uhat;

#define RISSUE(jv, sl)                                                   \
    do {                                                                 \
        CP16(dst0 + (sl) * 5376, gu + (size_t)(jv) * 20480 + so0);       \
        if (has1) CP16(dst1 + (sl) * 5376, gu + (size_t)(jv) * 20480 + so1); \
    } while (0)

#pragma unroll
    for (int s = 0; s < 7; s++) {
        if (s < njs) RISSUE(jbeg + s, s);
        CP_COMMIT();
    }

    // fused squash prologue -> vs (fp16 pairs)
    __half2 vs2[8];
    {
        const int row = (b * NN + (act ? n : 0)) * OD;
        float vsf[OD];
        {
            const float4* p0 = (const float4*)(g_s0 + row);
            float sv[OD];
#pragma unroll
            for (int k = 0; k < 4; k++) {
                float4 v = p0[k];
                sv[4 * k] = v.x; sv[4 * k + 1] = v.y;
                sv[4 * k + 2] = v.z; sv[4 * k + 3] = v.w;
            }
            float sc = squash_scale(sv);
#pragma unroll
            for (int o = 0; o < OD; o++) vsf[o] = sc * sv[o];
        }
        if (pass == 2) {
            const float4* p1 = (const float4*)(g_s1 + row);
            float sv[OD];
#pragma unroll
            for (int k = 0; k < 4; k++) {
                float4 v = p1[k];
                sv[4 * k] = v.x; sv[4 * k + 1] = v.y;
                sv[4 * k + 2] = v.z; sv[4 * k + 3] = v.w;
            }
            float sc = squash_scale(sv);
#pragma unroll
            for (int o = 0; o < OD; o++) vsf[o] = fmaf(sc, sv[o], vsf[o]);
        }
#pragma unroll
        for (int k = 0; k < 8; k++)
            vs2[k] = __floats2half2_rn(vsf[2 * k], vsf[2 * k + 1]);
    }

    float s_acc[OD];
#pragma unroll
    for (int o = 0; o < OD; o++) s_acc[o] = 0.f;

    const int nl = act ? n : 0;
    int slot = 0;
    for (int k = 0; k < njs; k++) {
        CP_WAIT6();
        __syncthreads();

        const char* tp = tile[slot] + bg * 336 + nl * 32;
        uint4 cA = *(const uint4*)tp;
        uint4 cB = *(const uint4*)(tp + 16);
        const __half2* hA = (const __half2*)&cA;
        const __half2* hB = (const __half2*)&cB;

        __half2 dA = __hmul2(hA[0], vs2[0]), dB = __hmul2(hB[0], vs2[4]);
#pragma unroll
        for (int q = 1; q < 4; q++) {
            dA = __hfma2(hA[q], vs2[q], dA);
            dB = __hfma2(hB[q], vs2[4 + q], dB);
        }
        __half2 ds = __hadd2(dA, dB);
        float d = __low2float(ds) + __high2float(ds);

        float e = act ? __expf(d) : 0.f;
        float sum = e;
#pragma unroll
        for (int m = 1; m < 16; m <<= 1)
            sum += __shfl_xor_sync(0xFFFFFFFFu, sum, m, 16);
        float c = __fdividef(e, sum);

#pragma unroll
        for (int q = 0; q < 4; q++) {
            float2 f = __half22float2(hA[q]);
            s_acc[2 * q] = fmaf(c, f.x, s_acc[2 * q]);
            s_acc[2 * q + 1] = fmaf(c, f.y, s_acc[2 * q + 1]);
            f = __half22float2(hB[q]);
            s_acc[8 + 2 * q] = fmaf(c, f.x, s_acc[8 + 2 * q]);
            s_acc[9 + 2 * q] = fmaf(c, f.y, s_acc[9 + 2 * q]);
        }

        if (k + 7 < njs) {
            int rs = slot + 7;
            if (rs >= 8) rs -= 8;
            RISSUE(jbeg + k + 7, rs);
        }
        CP_COMMIT();
        if (++slot == 8) slot = 0;
    }
#undef RISSUE

    if (act) {
        float* sp = ((pass == 1) ? g_s1 : g_s2) + (b * NN + n) * OD;
#pragma unroll
        for (int o = 0; o < OD; o++) atomicAdd(sp + o, s_acc[o]);
    }
}

// ─────────────────── Final: v2 = squash(s2) -> output ───────────────────────
__global__ void k_squash_out(float* __restrict__ out) {
    int t = threadIdx.x;
    if (t >= BB * NN) return;
    const float4* sp = (const float4*)(g_s2 + t * OD);
    float4 a = sp[0], b4 = sp[1], c4 = sp[2], d4 = sp[3];
    float s[OD] = {a.x, a.y, a.z, a.w, b4.x, b4.y, b4.z, b4.w,
                   c4.x, c4.y, c4.z, c4.w, d4.x, d4.y, d4.z, d4.w};
    float sc = squash_scale(s);
    float4* op = (float4*)(out + t * OD);
    op[0] = make_float4(sc * s[0], sc * s[1], sc * s[2], sc * s[3]);
    op[1] = make_float4(sc * s[4], sc * s[5], sc * s[6], sc * s[7]);
    op[2] = make_float4(sc * s[8], sc * s[9], sc * s[10], sc * s[11]);
    op[3] = make_float4(sc * s[12], sc * s[13], sc * s[14], sc * s[15]);
}

extern "C" void kernel_launch(void* const* d_in, const int* in_sizes, int n_in,
                              void* d_out, int out_size) {
    const float* x = (const float*)d_in[0];  // [64, 6912, 16]
    const float* W = (const float*)d_in[1];  // [10, 6912, 16, 16]
    float* out = (float*)d_out;              // [64, 10, 16]

    // >48KB dynamic smem opt-in (host attribute set; no allocation)
    cudaFuncSetAttribute(k_uhat, cudaFuncAttributeMaxDynamicSharedMemorySize,
                         UHAT_SMEM);

    k_xt<<<IC / JT, 256>>>(x);               // x -> fp16 [j][i][b]; zero s bufs
    k_uhat<<<IC / JB, NTH, UHAT_SMEM>>>(W);  // u_hat (fp16) + fused s0
    k_route<<<RT_BLOCKS, RT_TH>>>(1);        // squash(s0); emit s1
    k_route<<<RT_BLOCKS, RT_TH>>>(2);        // squash(s0)+squash(s1); emit s2
    k_squash_out<<<1, 640>>>(out);           // v2 -> output
}

// round 10
// speedup vs baseline: 1.7425x; 1.0157x over previous
#include <cuda_runtime.h>
#include <cuda_fp16.h>
#include <math.h>

#define BB 64
#define NN 10
#define ID 16
#define OD 16
#define IC 6912
#define JB 24          // j-tile for k_uhat (grid 288, 2 blocks/SM)
#define NTH 320        // k_uhat: warp = n; lane owns b = 2lane, 2lane+1
#define JT 16          // j's per k_xt block
#define RT_TH 256      // k_route: 16-lane groups, n = tid&15
#define RT_BLOCKS 444  // persistent: 148 SMs x 3
#define UHAT_SMEM (40960 + 40960)  // W rings + out staging

// Packed f32x2 helpers (sm_100+ PTX)
#define FFMA2(d, a, b) asm("fma.rn.f32x2 %0, %1, %2, %0;" : "+l"(d) : "l"(a), "l"(b))
#define FADD2(d, a)    asm("add.rn.f32x2 %0, %0, %1;"     : "+l"(d) : "l"(a))
// cp.async (LDGSTS)
#define CP16(dst, src) asm volatile("cp.async.ca.shared.global [%0], [%1], 16;" \
                                    :: "r"(dst), "l"(src))
#define CP_COMMIT()    asm volatile("cp.async.commit_group;")
#define CP_WAIT2()     asm volatile("cp.async.wait_group 2;")
// bulk shared->global store
#define BULK_ST(gdst, ssrc, bytes)                                             \
    asm volatile("cp.async.bulk.global.shared::cta.bulk_group [%0], [%1], %2;" \
                 :: "l"(gdst), "r"(ssrc), "r"(bytes) : "memory")
#define BULK_COMMIT()  asm volatile("cp.async.bulk.commit_group;")
#define BULK_WAIT_RD1() asm volatile("cp.async.bulk.wait_group.read 1;")
#define BULK_WAIT0()   asm volatile("cp.async.bulk.wait_group 0;")
#define FENCE_ASYNC()  asm volatile("fence.proxy.async.shared::cta;" ::: "memory")

// Scratch (device globals: allocation-free). u_hat fp16, layout [j][n][b][o].
__device__ __half g_uhat[(size_t)IC * NN * BB * OD];
__device__ __half g_xh[(size_t)IC * ID * BB];  // x fp16, [j][i][b]
__device__ float g_s0[BB * NN * OD];           // s from pass 0
__device__ float g_s1[BB * NN * OD];           // s from pass 1
__device__ float g_s2[BB * NN * OD];           // s from pass 2

// ───── Kernel T: x [b][j][i] fp32 -> g_xh [j][i][b] fp16; also zero g_s* ────
__global__ void k_xt(const float* __restrict__ x) {
    __shared__ __half th[ID][BB];
    const int tid = threadIdx.x;  // 256
    const int bid = blockIdx.x;
    if (bid < 30) {
        float* z = (bid < 10) ? g_s0 : (bid < 20) ? g_s1 : g_s2;
        int off = (bid % 10) * 1024;
#pragma unroll
        for (int r = 0; r < 4; r++) z[off + r * 256 + tid] = 0.f;
    }
    const int jb = bid * JT;
    for (int jj = 0; jj < JT; jj++) {
        const int j = jb + jj;
#pragma unroll
        for (int r = 0; r < 4; r++) {
            int e = r * 256 + tid;  // b = e>>4, i = e&15
            th[e & 15][e >> 4] =
                __float2half(x[((size_t)(e >> 4) * IC + j) * 16 + (e & 15)]);
        }
        __syncthreads();
#pragma unroll
        for (int r = 0; r < 2; r++) {
            int c = r * 256 + tid;          // u32 index: i = c>>5, b = (c&31)*2
            __half2 p = __halves2half2(th[c >> 5][(c & 31) * 2],
                                       th[c >> 5][(c & 31) * 2 + 1]);
            ((unsigned*)g_xh)[(size_t)j * 512 + c] = *(unsigned*)&p;
        }
        __syncthreads();
    }
}

// ───────────────────────────── Kernel A: u_hat GEMM ─────────────────────────
// W: per-warp 4-stage CP16 ring (warp-local syncs only). x: fp16, 16 coalesced
// LDG.32 per j. OUT: staged in smem, one 2KB cp.async.bulk per (j, n).
__global__ __launch_bounds__(NTH, 2) void k_uhat(const float* __restrict__ W) {
    extern __shared__ __align__(16) char dsm[];
    float* wsf = (float*)dsm;            // [10 warps][4 stages][256 f] = 40960B
    char* outs = dsm + 40960;            // [2 slots][10 n][2048B]     = 40960B
    const int tid = threadIdx.x;
    const int w = tid >> 5;       // warp = n
    const int lane = tid & 31;
    const int j0 = blockIdx.x * JB;

    const float* wsrc = W + (size_t)w * IC * 256;
    const unsigned wb_sh = (unsigned)__cvta_generic_to_shared(wsf + w * 1024);
    const unsigned d1 = wb_sh + lane * 16;
    const unsigned d2 = wb_sh + 512 + lane * 16;

#define WISSUE(jv, sv)                                   \
    do {                                                 \
        const float* s_ = wsrc + (size_t)(jv) * 256;     \
        CP16(d1 + (sv) * 1024, s_ + lane * 4);           \
        CP16(d2 + (sv) * 1024, s_ + lane * 4 + 128);     \
    } while (0)

#pragma unroll
    for (int s = 0; s < 3; s++) { WISSUE(j0 + s, s); CP_COMMIT(); }

    const unsigned outsh_base = (unsigned)__cvta_generic_to_shared(outs) +
                                w * 2048 + lane * 64;

    unsigned long long s2a[8], s2b[8];
#pragma unroll
    for (int k = 0; k < 8; k++) { s2a[k] = 0ull; s2b[k] = 0ull; }

    for (int jj = 0; jj < JB; jj++) {
        const int j = j0 + jj;
        const unsigned* xp = (const unsigned*)g_xh + (size_t)j * 512;
        unsigned x32[16];
#pragma unroll
        for (int i = 0; i < ID; i++) x32[i] = xp[i * 32 + lane];

        CP_WAIT2();
        __syncwarp();

        const ulonglong2* wb = (const ulonglong2*)(wsf + (w * 4 + (jj & 3)) * 256);

        unsigned long long u2a[8], u2b[8];
#pragma unroll
        for (int k = 0; k < 8; k++) { u2a[k] = 0ull; u2b[k] = 0ull; }
#pragma unroll
        for (int i = 0; i < ID; i++) {
            float2 fx = __half22float2(*(__half2*)&x32[i]);  // b=2lane, 2lane+1
            unsigned long long xa2, xb2;
            asm("mov.b64 %0, {%1, %1};" : "=l"(xa2) : "f"(fx.x));
            asm("mov.b64 %0, {%1, %1};" : "=l"(xb2) : "f"(fx.y));
            ulonglong2 p0 = wb[i * 4 + 0], p1 = wb[i * 4 + 1];
            ulonglong2 p2 = wb[i * 4 + 2], p3 = wb[i * 4 + 3];
            FFMA2(u2a[0], xa2, p0.x); FFMA2(u2a[1], xa2, p0.y);
            FFMA2(u2a[2], xa2, p1.x); FFMA2(u2a[3], xa2, p1.y);
            FFMA2(u2a[4], xa2, p2.x); FFMA2(u2a[5], xa2, p2.y);
            FFMA2(u2a[6], xa2, p3.x); FFMA2(u2a[7], xa2, p3.y);
            FFMA2(u2b[0], xb2, p0.x); FFMA2(u2b[1], xb2, p0.y);
            FFMA2(u2b[2], xb2, p1.x); FFMA2(u2b[3], xb2, p1.y);
            FFMA2(u2b[4], xb2, p2.x); FFMA2(u2b[5], xb2, p2.y);
            FFMA2(u2b[6], xb2, p3.x); FFMA2(u2b[7], xb2, p3.y);
        }

        {
            __align__(16) __half2 ha[8], hb[8];
#pragma unroll
            for (int k = 0; k < 8; k++) {
                float lo, hi;
                asm("mov.b64 {%0, %1}, %2;" : "=f"(lo), "=f"(hi) : "l"(u2a[k]));
                ha[k] = __floats2half2_rn(lo, hi);
                asm("mov.b64 {%0, %1}, %2;" : "=f"(lo), "=f"(hi) : "l"(u2b[k]));
                hb[k] = __floats2half2_rn(lo, hi);
            }
            if (lane == 0) BULK_WAIT_RD1();
            __syncwarp();
            const unsigned ob = outsh_base + (jj & 1) * 20480;
            asm volatile("st.shared.v4.b32 [%0], {%1,%2,%3,%4};" :: "r"(ob),
                "r"(*(unsigned*)&ha[0]), "r"(*(unsigned*)&ha[1]),
                "r"(*(unsigned*)&ha[2]), "r"(*(unsigned*)&ha[3]));
            asm volatile("st.shared.v4.b32 [%0], {%1,%2,%3,%4};" :: "r"(ob + 16),
                "r"(*(unsigned*)&ha[4]), "r"(*(unsigned*)&ha[5]),
                "r"(*(unsigned*)&ha[6]), "r"(*(unsigned*)&ha[7]));
            asm volatile("st.shared.v4.b32 [%0], {%1,%2,%3,%4};" :: "r"(ob + 32),
                "r"(*(unsigned*)&hb[0]), "r"(*(unsigned*)&hb[1]),
                "r"(*(unsigned*)&hb[2]), "r"(*(unsigned*)&hb[3]));
            asm volatile("st.shared.v4.b32 [%0], {%1,%2,%3,%4};" :: "r"(ob + 48),
                "r"(*(unsigned*)&hb[4]), "r"(*(unsigned*)&hb[5]),
                "r"(*(unsigned*)&hb[6]), "r"(*(unsigned*)&hb[7]));
            __syncwarp();
            if (lane == 0) {
                FENCE_ASYNC();
                const char* gdst = (const char*)g_uhat + ((size_t)j * NN + w) * 2048;
                unsigned ssrc = (unsigned)__cvta_generic_to_shared(outs) +
                                (jj & 1) * 20480 + w * 2048;
                BULK_ST(gdst, ssrc, 2048);
                BULK_COMMIT();
            }
#pragma unroll
            for (int k = 0; k < 8; k++) { FADD2(s2a[k], u2a[k]); FADD2(s2b[k], u2b[k]); }
        }

        if (jj + 3 < JB) WISSUE(j0 + jj + 3, (jj + 3) & 3);
        CP_COMMIT();
    }
#undef WISSUE
    if (lane == 0) BULK_WAIT0();

    const int b0 = 2 * lane;
    float* spa = g_s0 + (b0 * NN + w) * OD;
    float* spb = g_s0 + ((b0 + 1) * NN + w) * OD;
#pragma unroll
    for (int k = 0; k < 8; k++) {
        float lo, hi;
        asm("mov.b64 {%0, %1}, %2;" : "=f"(lo), "=f"(hi) : "l"(s2a[k]));
        atomicAdd(spa + 2 * k, 0.1f * lo);
        atomicAdd(spa + 2 * k + 1, 0.1f * hi);
        asm("mov.b64 {%0, %1}, %2;" : "=f"(lo), "=f"(hi) : "l"(s2b[k]));
        atomicAdd(spb + 2 * k, 0.1f * lo);
        atomicAdd(spb + 2 * k + 1, 0.1f * hi);
    }
}

// squash scale for one 16-float s vector
__device__ __forceinline__ float squash_scale(const float* s) {
    float s2 = 0.f;
#pragma unroll
    for (int o = 0; o < OD; o++) s2 = fmaf(s[o], s[o], s2);
    return (s2 / (1.f + s2)) * rsqrtf(s2 + 1e-7f);
}

// ───────────────────── Kernel C: PERSISTENT routing pass ────────────────────
// 2-j SUPER-STAGES: one __syncthreads per 2 j's; the two shfl softmax chains
// interleave (one chain latency per pair). Ring = 8 j-slots consumed in
// aligned pairs; 3 supers (31.5 KB) in flight. Work split by j-pairs.
__global__ __launch_bounds__(RT_TH, 3) void k_route(int pass) {
    __shared__ __align__(16) char tile[8][5376];  // per j: 16 b x 336 B (pad)
    const int tid = threadIdx.x;
    const int n = tid & 15;
    const int bg = tid >> 4;
    const int bgrp = blockIdx.x & 3;
    const int idx = blockIdx.x >> 2;                   // 0..110
    const int pbeg = (idx * (IC / 2)) / 111;
    const int pend = ((idx + 1) * (IC / 2)) / 111;
    const int nsup = pend - pbeg;                      // 31..32 supers (2 j each)
    const int jbeg = 2 * pbeg;
    const int b = bgrp * 16 + bg;
    const bool act = (n < NN);

    // copy plan: 320 x 16B chunks/j; layout [j][n][b][o] -> 2048B per (j,n)
    const int c0 = tid, c1 = tid + 256;
    const bool has1 = (c1 < 320);
    const unsigned tb = (unsigned)__cvta_generic_to_shared(&tile[0][0]);
    const int n0 = c0 >> 5, t0 = c0 & 31, bg0 = t0 >> 1, hf0 = t0 & 1;
    const int n1 = c1 >> 5, t1 = c1 & 31, bg1 = t1 >> 1, hf1 = t1 & 1;
    const unsigned dst0 = tb + bg0 * 336 + n0 * 32 + hf0 * 16;
    const unsigned dst1 = tb + bg1 * 336 + n1 * 32 + hf1 * 16;
    const size_t so0 = (size_t)n0 * 2048 + (bgrp * 16 + bg0) * 32 + hf0 * 16;
    const size_t so1 = (size_t)n1 * 2048 + (bgrp * 16 + bg1) * 32 + hf1 * 16;
    const char* gu = (const char*)g_uhat;

#define RISSUE(jv, sl)                                                       \
    do {                                                                     \
        CP16(dst0 + (sl) * 5376, gu + (size_t)(jv) * 20480 + so0);           \
        if (has1) CP16(dst1 + (sl) * 5376, gu + (size_t)(jv) * 20480 + so1); \
    } while (0)

#pragma unroll
    for (int sp = 0; sp < 3; sp++) {  // 3 super-stages in flight
        if (sp < nsup) { RISSUE(jbeg + 2 * sp, 2 * sp); RISSUE(jbeg + 2 * sp + 1, 2 * sp + 1); }
        CP_COMMIT();
    }

    // fused squash prologue -> vs (fp16 pairs)
    __half2 vs2[8];
    {
        const int row = (b * NN + (act ? n : 0)) * OD;
        float vsf[OD];
        {
            const float4* p0 = (const float4*)(g_s0 + row);
            float sv[OD];
#pragma unroll
            for (int k = 0; k < 4; k++) {
                float4 v = p0[k];
                sv[4 * k] = v.x; sv[4 * k + 1] = v.y;
                sv[4 * k + 2] = v.z; sv[4 * k + 3] = v.w;
            }
            float sc = squash_scale(sv);
#pragma unroll
            for (int o = 0; o < OD; o++) vsf[o] = sc * sv[o];
        }
        if (pass == 2) {
            const float4* p1 = (const float4*)(g_s1 + row);
            float sv[OD];
#pragma unroll
            for (int k = 0; k < 4; k++) {
                float4 v = p1[k];
                sv[4 * k] = v.x; sv[4 * k + 1] = v.y;
                sv[4 * k + 2] = v.z; sv[4 * k + 3] = v.w;
            }
            float sc = squash_scale(sv);
#pragma unroll
            for (int o = 0; o < OD; o++) vsf[o] = fmaf(sc, sv[o], vsf[o]);
        }
#pragma unroll
        for (int k = 0; k < 8; k++)
            vs2[k] = __floats2half2_rn(vsf[2 * k], vsf[2 * k + 1]);
    }

    float s_acc[OD];
#pragma unroll
    for (int o = 0; o < OD; o++) s_acc[o] = 0.f;

    const int nl = act ? n : 0;
    for (int k = 0; k < nsup; k++) {
        CP_WAIT2();        // super k landed
        __syncthreads();   // visible to all; prior super's reads done

        const int s = (2 * k) & 7;  // even slot; pair = s, s+1 (no wrap)
        const char* tp0 = tile[s] + bg * 336 + nl * 32;
        const char* tp1 = tile[s + 1] + bg * 336 + nl * 32;
        uint4 cA0 = *(const uint4*)tp0;
        uint4 cB0 = *(const uint4*)(tp0 + 16);
        uint4 cA1 = *(const uint4*)tp1;
        uint4 cB1 = *(const uint4*)(tp1 + 16);
        const __half2* hA0 = (const __half2*)&cA0;
        const __half2* hB0 = (const __half2*)&cB0;
        const __half2* hA1 = (const __half2*)&cA1;
        const __half2* hB1 = (const __half2*)&cB1;

        __half2 dA0 = __hmul2(hA0[0], vs2[0]), dB0 = __hmul2(hB0[0], vs2[4]);
        __half2 dA1 = __hmul2(hA1[0], vs2[0]), dB1 = __hmul2(hB1[0], vs2[4]);
#pragma unroll
        for (int q = 1; q < 4; q++) {
            dA0 = __hfma2(hA0[q], vs2[q], dA0); dB0 = __hfma2(hB0[q], vs2[4 + q], dB0);
            dA1 = __hfma2(hA1[q], vs2[q], dA1); dB1 = __hfma2(hB1[q], vs2[4 + q], dB1);
        }
        __half2 ds0 = __hadd2(dA0, dB0), ds1 = __hadd2(dA1, dB1);
        float d0 = __low2float(ds0) + __high2float(ds0);
        float d1 = __low2float(ds1) + __high2float(ds1);

        float e0 = act ? __expf(d0) : 0.f;
        float e1 = act ? __expf(d1) : 0.f;
        float s0 = e0, s1 = e1;
#pragma unroll
        for (int m = 1; m < 16; m <<= 1) {  // interleaved chains
            s0 += __shfl_xor_sync(0xFFFFFFFFu, s0, m, 16);
            s1 += __shfl_xor_sync(0xFFFFFFFFu, s1, m, 16);
        }
        float c0 = __fdividef(e0, s0);
        float c1 = __fdividef(e1, s1);

#pragma unroll
        for (int q = 0; q < 4; q++) {
            float2 f = __half22float2(hA0[q]);
            s_acc[2 * q] = fmaf(c0, f.x, s_acc[2 * q]);
            s_acc[2 * q + 1] = fmaf(c0, f.y, s_acc[2 * q + 1]);
            f = __half22float2(hB0[q]);
            s_acc[8 + 2 * q] = fmaf(c0, f.x, s_acc[8 + 2 * q]);
            s_acc[9 + 2 * q] = fmaf(c0, f.y, s_acc[9 + 2 * q]);
            f = __half22float2(hA1[q]);
            s_acc[2 * q] = fmaf(c1, f.x, s_acc[2 * q]);
            s_acc[2 * q + 1] = fmaf(c1, f.y, s_acc[2 * q + 1]);
            f = __half22float2(hB1[q]);
            s_acc[8 + 2 * q] = fmaf(c1, f.x, s_acc[8 + 2 * q]);
            s_acc[9 + 2 * q] = fmaf(c1, f.y, s_acc[9 + 2 * q]);
        }

        const int kn = k + 3;
        if (kn < nsup) {
            const int sn = (2 * kn) & 7;
            RISSUE(jbeg + 2 * kn, sn);
            RISSUE(jbeg + 2 * kn + 1, sn + 1);
        }
        CP_COMMIT();
    }
#undef RISSUE

    if (act) {
        float* sp = ((pass == 1) ? g_s1 : g_s2) + (b * NN + n) * OD;
#pragma unroll
        for (int o = 0; o < OD; o++) atomicAdd(sp + o, s_acc[o]);
    }
}

// ─────────────────── Final: v2 = squash(s2) -> output ───────────────────────
__global__ void k_squash_out(float* __restrict__ out) {
    int t = threadIdx.x;
    if (t >= BB * NN) return;
    const float4* sp = (const float4*)(g_s2 + t * OD);
    float4 a = sp[0], b4 = sp[1], c4 = sp[2], d4 = sp[3];
    float s[OD] = {a.x, a.y, a.z, a.w, b4.x, b4.y, b4.z, b4.w,
                   c4.x, c4.y, c4.z, c4.w, d4.x, d4.y, d4.z, d4.w};
    float sc = squash_scale(s);
    float4* op = (float4*)(out + t * OD);
    op[0] = make_float4(sc * s[0], sc * s[1], sc * s[2], sc * s[3]);
    op[1] = make_float4(sc * s[4], sc * s[5], sc * s[6], sc * s[7]);
    op[2] = make_float4(sc * s[8], sc * s[9], sc * s[10], sc * s[11]);
    op[3] = make_float4(sc * s[12], sc * s[13], sc * s[14], sc * s[15]);
}

extern "C" void kernel_launch(void* const* d_in, const int* in_sizes, int n_in,
                              void* d_out, int out_size) {
    const float* x = (const float*)d_in[0];  // [64, 6912, 16]
    const float* W = (const float*)d_in[1];  // [10, 6912, 16, 16]
    float* out = (float*)d_out;              // [64, 10, 16]

    cudaFuncSetAttribute(k_uhat, cudaFuncAttributeMaxDynamicSharedMemorySize,
                         UHAT_SMEM);

    k_xt<<<IC / JT, 256>>>(x);               // x -> fp16 [j][i][b]; zero s bufs
    k_uhat<<<IC / JB, NTH, UHAT_SMEM>>>(W);  // u_hat (fp16) + fused s0
    k_route<<<RT_BLOCKS, RT_TH>>>(1);        // squash(s0); emit s1
    k_route<<<RT_BLOCKS, RT_TH>>>(2);        // squash(s0)+squash(s1); emit s2
    k_squash_out<<<1, 640>>>(out);           // v2 -> output
}